// round 11
// baseline (speedup 1.0000x reference)
#include <cuda_runtime.h>
#include <cuda_bf16.h>
#include <math.h>
#include <stdint.h>

#define BH   24
#define TT   2048
#define NN   256
#define CC   128
#define NCH  16

// ---------------- device scratch ----------------------------------------------
__device__ float g_tabc[TT * (NN/2)];
__device__ float g_tabs[TT * (NN/2)];
__device__ float g_S[BH*NCH*NN*NN];
__device__ __nv_bfloat16 g_Sh[BH*NCH*NN*NN], g_Sl[BH*NCH*NN*NN];
__device__ unsigned g_ctr_a, g_ctr_k;          // persistent-kernel tile counters

// ---------------- PTX helpers ---------------------------------------------------
__device__ __forceinline__ uint32_t smem_u32(const void* p) {
    uint32_t a;
    asm("{ .reg .u64 t; cvta.to.shared.u64 t, %1; cvt.u32.u64 %0, t; }" : "=r"(a) : "l"(p));
    return a;
}
__device__ __forceinline__ void cpa16(uint32_t s, const void* g) {
    asm volatile("cp.async.cg.shared.global [%0], [%1], 16;" :: "r"(s), "l"(g));
}
#define CP_COMMIT() asm volatile("cp.async.commit_group;" ::: "memory")
#define CP_WAIT0()  asm volatile("cp.async.wait_group 0;" ::: "memory")
#define CP_WAIT1()  asm volatile("cp.async.wait_group 1;" ::: "memory")

__device__ __forceinline__ void ldsm4(uint32_t* r, uint32_t a) {
    asm volatile("ldmatrix.sync.aligned.m8n8.x4.shared.b16 {%0,%1,%2,%3}, [%4];"
        : "=r"(r[0]), "=r"(r[1]), "=r"(r[2]), "=r"(r[3]) : "r"(a));
}
__device__ __forceinline__ void ldsm4t(uint32_t* r, uint32_t a) {
    asm volatile("ldmatrix.sync.aligned.m8n8.x4.trans.shared.b16 {%0,%1,%2,%3}, [%4];"
        : "=r"(r[0]), "=r"(r[1]), "=r"(r[2]), "=r"(r[3]) : "r"(a));
}
__device__ __forceinline__ void mma_bf16(float* d, const uint32_t* a, const uint32_t* b) {
    asm volatile("mma.sync.aligned.m16n8k16.row.col.f32.bf16.bf16.f32 "
        "{%0,%1,%2,%3}, {%4,%5,%6,%7}, {%8,%9}, {%0,%1,%2,%3};"
        : "+f"(d[0]), "+f"(d[1]), "+f"(d[2]), "+f"(d[3])
        : "r"(a[0]), "r"(a[1]), "r"(a[2]), "r"(a[3]), "r"(b[0]), "r"(b[1]));
}

// ---------------- split / rope helpers (packed cvt path) ------------------------
__device__ __forceinline__ void split2(float x, float y, uint32_t& h, uint32_t& l) {
    uint32_t hb;
    asm("cvt.rn.bf16x2.f32 %0, %1, %2;" : "=r"(hb) : "f"(y), "f"(x));
    float hx = __uint_as_float(hb << 16);
    float hy = __uint_as_float(hb & 0xFFFF0000u);
    float lx = x - hx, ly = y - hy;
    asm("cvt.rn.bf16x2.f32 %0, %1, %2;" : "=r"(l) : "f"(ly), "f"(lx));
    h = hb;
}
__device__ __forceinline__ void rope_split8_cs(const float* __restrict__ src,
                                               float4 c, float4 s,
                                               uint4& hi, uint4& lo) {
    float4 a = *(const float4*)(src);
    float4 b = *(const float4*)(src + 4);
    float r0 = a.x*c.x - a.y*s.x, r1 = a.y*c.x + a.x*s.x;
    float r2 = a.z*c.y - a.w*s.y, r3 = a.w*c.y + a.z*s.y;
    float r4 = b.x*c.z - b.y*s.z, r5 = b.y*c.z + b.x*s.z;
    float r6 = b.z*c.w - b.w*s.w, r7 = b.w*c.w + b.z*s.w;
    split2(r0, r1, hi.x, lo.x); split2(r2, r3, hi.y, lo.y);
    split2(r4, r5, hi.z, lo.z); split2(r6, r7, hi.w, lo.w);
}
__device__ __forceinline__ void rope_split8(const float* __restrict__ src, int t, int f,
                                            uint4& hi, uint4& lo) {
    float4 c = *(const float4*)(g_tabc + t * 128 + (f >> 1));
    float4 s = *(const float4*)(g_tabs + t * 128 + (f >> 1));
    rope_split8_cs(src, c, s, hi, lo);
}
__device__ __forceinline__ void split8(const float* __restrict__ src, uint4& hi, uint4& lo) {
    float4 a = *(const float4*)(src);
    float4 b = *(const float4*)(src + 4);
    split2(a.x, a.y, hi.x, lo.x); split2(a.z, a.w, hi.y, lo.y);
    split2(b.x, b.y, hi.z, lo.z); split2(b.z, b.w, hi.w, lo.w);
}

// ---------------- kernel 1: RoPE phase tables (+ counter reset) -----------------
__global__ void k_tables() {
    int id = blockIdx.x * blockDim.x + threadIdx.x;
    if (id == 0) { g_ctr_a = 0u; g_ctr_k = 0u; }
    if (id >= TT * (NN/2)) return;
    int t = id >> 7;
    int j = id & 127;
    double fr_d = exp2(-(double)j / 8.0) / (2.0 * 3.14159265358979323846);
    float f32 = (float)fr_d;
    float ph  = (float)t * f32;
    ph = ph - floorf(ph);
    float ang = ph * 6.28318530717958647692f;
    double angd = (double)ang;
    g_tabc[id] = (float)cos(angd);
    g_tabs[id] = (float)sin(angd);
}

// ---------------- kernel 2: chunk KV state (persistent, fused rope) -------------
#define KV_BUF_A 17408
#define KV_BUF_B 33792
#define KV_B0    34816
#define SMEM_KV  102400
#define KV_TILES (BH * 15 * 2)

__global__ void __launch_bounds__(512, 1) k_kv(const float* __restrict__ K,
                                               const float* __restrict__ V) {
    extern __shared__ char sm[];
    __shared__ unsigned s_tile;
    uint32_t sb = smem_u32(sm);
    int tid = threadIdx.x, lane = tid & 31, wid = tid >> 5;
    int wm = wid >> 2, wn = wid & 3;
    int l16 = lane >> 4, lmod8 = lane & 7, l8 = (lane >> 3) & 1;
    int lq = lane >> 2, lr2 = (lane & 3) * 2;

    int ar = tid >> 4, ac8 = tid & 15;
    uint32_t a_so = (uint32_t)(ar * 272 + ac8 * 16);
    int vr = tid >> 5, vc8 = tid & 31;
    uint32_t v_so = (uint32_t)(vr * 528 + vc8 * 16);

    const float *Kp, *Vp;
    int m0g, t0;

    uint4 ahi, alo, vhi0, vlo0, vhi1, vlo1;
    auto loadSlab = [&](int sl) {
        int tk = t0 + sl * 32 + ar;
        rope_split8(Kp + (size_t)(sl * 32 + ar) * NN + m0g + ac8 * 8,
                    tk, m0g + ac8 * 8, ahi, alo);
        split8(Vp + (size_t)(sl * 32 + vr) * NN + vc8 * 8, vhi0, vlo0);
        split8(Vp + (size_t)(sl * 32 + vr + 16) * NN + vc8 * 8, vhi1, vlo1);
    };
    auto storeSlab = [&](int buf) {
        char* ab = sm + buf * KV_BUF_A;
        *(uint4*)(ab + a_so) = ahi;
        *(uint4*)(ab + 8704 + a_so) = alo;
        char* bb = sm + KV_B0 + buf * KV_BUF_B;
        *(uint4*)(bb + v_so) = vhi0;
        *(uint4*)(bb + 16896 + v_so) = vlo0;
        *(uint4*)(bb + 8448 + v_so) = vhi1;
        *(uint4*)(bb + 16896 + 8448 + v_so) = vlo1;
    };

    for (;;) {
        if (tid == 0) s_tile = atomicAdd(&g_ctr_k, 1u);
        __syncthreads();
        unsigned t = s_tile;
        if (t >= KV_TILES) break;
        int pair = t >> 1;
        int bh = pair / 15, ch = pair % 15;
        m0g = (t & 1) * 128;
        t0 = ch * CC;
        Kp = K + (size_t)(bh * TT + t0) * NN;
        Vp = V + (size_t)(bh * TT + t0) * NN;

        float acc[2][8][4];
#pragma unroll
        for (int a = 0; a < 2; a++)
#pragma unroll
            for (int b = 0; b < 8; b++)
#pragma unroll
                for (int c = 0; c < 4; c++) acc[a][b][c] = 0.f;

        loadSlab(0);
        storeSlab(0);
        __syncthreads();
        for (int sl = 0; sl < 4; sl++) {
            if (sl < 3) loadSlab(sl + 1);
            uint32_t ab = sb + (sl & 1) * KV_BUF_A;
            uint32_t bb = sb + KV_B0 + (sl & 1) * KV_BUF_B;
#pragma unroll
            for (int k0 = 0; k0 < 32; k0 += 16) {
                uint32_t ah[2][4], al[2][4];
#pragma unroll
                for (int mt = 0; mt < 2; mt++) {
                    uint32_t off = (uint32_t)(((k0 + lmod8 + 8 * l16) * 136 +
                                               wm * 32 + mt * 16 + 8 * l8) * 2);
                    ldsm4t(ah[mt], ab + off);
                    ldsm4t(al[mt], ab + 8704 + off);
                }
#pragma unroll
                for (int np = 0; np < 4; np++) {
                    uint32_t bh2[4], bl2[4];
                    uint32_t off = (uint32_t)(((k0 + lmod8 + 8 * l8) * 264 +
                                               wn * 64 + np * 16 + 8 * l16) * 2);
                    ldsm4t(bh2, bb + off);
                    ldsm4t(bl2, bb + 16896 + off);
#pragma unroll
                    for (int mt = 0; mt < 2; mt++) {
                        mma_bf16(acc[mt][2*np],   ah[mt], bh2);
                        mma_bf16(acc[mt][2*np],   ah[mt], bl2);
                        mma_bf16(acc[mt][2*np],   al[mt], bh2);
                        mma_bf16(acc[mt][2*np+1], ah[mt], bh2 + 2);
                        mma_bf16(acc[mt][2*np+1], ah[mt], bl2 + 2);
                        mma_bf16(acc[mt][2*np+1], al[mt], bh2 + 2);
                    }
                }
            }
            if (sl < 3) { storeSlab((sl + 1) & 1); __syncthreads(); }
        }
        float* Sp = g_S + (size_t)(bh * NCH + ch) * (NN * NN);
#pragma unroll
        for (int mt = 0; mt < 2; mt++)
#pragma unroll
            for (int nt = 0; nt < 8; nt++)
#pragma unroll
                for (int h = 0; h < 2; h++) {
                    int rr = m0g + wm * 32 + mt * 16 + lq + 8 * h;
                    int cc = wn * 64 + nt * 8 + lr2;
                    float2 o; o.x = acc[mt][nt][2*h]; o.y = acc[mt][nt][2*h+1];
                    *(float2*)(Sp + (size_t)rr * NN + cc) = o;
                }
        // next tile's grab-sync orders smem reuse
    }
}

// ---------------- kernel 3: exclusive prefix scan + bf16 split (MLP) ------------
__global__ void k_scan() {
    int g = blockIdx.x * blockDim.x + threadIdx.x;
    if (g >= BH * NN * NN / 4) return;
    int bh = g >> 14;
    int e4 = (g & 16383) << 2;
    size_t base = (size_t)bh * NCH * (NN * NN) + e4;
    float4 vals[NCH - 1];
#pragma unroll
    for (int i = 0; i < NCH - 1; i++)
        vals[i] = *(const float4*)(g_S + base + (size_t)i * (NN * NN));
    float r0 = 0.f, r1 = 0.f, r2 = 0.f, r3 = 0.f;
#pragma unroll
    for (int i = 0; i < NCH; i++) {
        size_t p = base + (size_t)i * (NN * NN);
        uint32_t h01, l01, h23, l23;
        split2(r0, r1, h01, l01);
        split2(r2, r3, h23, l23);
        uint2 H; H.x = h01; H.y = h23;
        uint2 L; L.x = l01; L.y = l23;
        *(uint2*)(g_Sh + p) = H;
        *(uint2*)(g_Sl + p) = L;
        if (i < NCH - 1) { r0 += vals[i].x; r1 += vals[i].y; r2 += vals[i].z; r3 += vals[i].w; }
    }
}

// ---------------- kernel 4: persistent Out = QR@S + tril(QR@KR^T)@V -------------
#define AT_BUF_A 20480
#define AT_B0    40960
#define AT_BUF_B 33792
#define AT_PH    142336          /* 40960 + 3*33792 */
#define AT_PL    177152
#define SMEM_ATTN 211968
#define AT_TILES (BH * NCH)

// stage-1 warp->tile LUT (10 live lower-triangle tiles, 3/3/2/2 per SMSP)
#define S1_R_PACK 981476u
#define S1_C_PACK 54436u

__global__ void __launch_bounds__(512, 1) k_attn(const float* __restrict__ Q,
                                                 const float* __restrict__ K,
                                                 const float* __restrict__ V,
                                                 float* __restrict__ out) {
    extern __shared__ char sm[];
    __shared__ unsigned s_tile;
    uint32_t sb = smem_u32(sm);
    int tid = threadIdx.x, lane = tid & 31, wid = tid >> 5;
    int wm = wid >> 2, wn = wid & 3;
    int lm16 = lane & 15, l16 = lane >> 4, lmod8 = lane & 7, l8 = (lane >> 3) & 1;
    int lq = lane >> 2, lr2 = (lane & 3) * 2;

    int pr = (S1_R_PACK >> (wid * 2)) & 3;
    int pc = (S1_C_PACK >> (wid * 2)) & 3;
    bool act1 = (wid < 10);

    int sr = tid >> 2, sc8 = tid & 3;
    uint32_t s_so = (uint32_t)(sr * 80 + sc8 * 16);
    int vr = tid >> 5, vc8 = tid & 31;
    uint32_t v_so = (uint32_t)(vr * 528 + vc8 * 16);

    const float *Qp, *Kp, *Vp;
    const __nv_bfloat16 *Sh, *Sl;
    int t0;

    uint4 qhi, qlo, khi, klo;
    auto loadQK = [&](int sl) {
        int f = sl * 32 + sc8 * 8;
        float4 c = *(const float4*)(g_tabc + (t0 + sr) * 128 + (f >> 1));
        float4 s = *(const float4*)(g_tabs + (t0 + sr) * 128 + (f >> 1));
        rope_split8_cs(Qp + (size_t)sr * NN + f, c, s, qhi, qlo);
        rope_split8_cs(Kp + (size_t)sr * NN + f, c, s, khi, klo);
    };
    auto storeQK = [&](int buf) {
        char* ab = sm + buf * AT_BUF_A;
        *(uint4*)(ab + s_so) = qhi;
        *(uint4*)(ab + 10240 + s_so) = qlo;
        char* bb = sm + AT_B0 + buf * AT_BUF_B;
        *(uint4*)(bb + s_so) = khi;
        *(uint4*)(bb + 16896 + s_so) = klo;
    };
    auto loadQ2 = [&](int sl) {
        int f = sl * 32 + sc8 * 8;
        float4 c = *(const float4*)(g_tabc + (t0 + sr) * 128 + (f >> 1));
        float4 s = *(const float4*)(g_tabs + (t0 + sr) * 128 + (f >> 1));
        rope_split8_cs(Qp + (size_t)sr * NN + f, c, s, qhi, qlo);
    };
    auto storeQ2 = [&](int buf) {
        char* ab = sm + buf * AT_BUF_A;
        *(uint4*)(ab + s_so) = qhi;
        *(uint4*)(ab + 10240 + s_so) = qlo;
    };
    auto cpS = [&](int buf, int sl) {
        uint32_t bb = sb + AT_B0 + buf * AT_BUF_B;
        int f0 = sl * 32;
#pragma unroll
        for (int v = tid; v < 1024; v += 512) {
            int r = v >> 5, c8 = v & 31;
            uint32_t so = (uint32_t)(r * 528 + c8 * 16);
            cpa16(bb + so,         Sh + (size_t)(f0 + r) * NN + c8 * 8);
            cpa16(bb + 16896 + so, Sl + (size_t)(f0 + r) * NN + c8 * 8);
        }
    };
    uint4 vhi0, vlo0, vhi1, vlo1;
    auto loadV3 = [&](int sl) {
        split8(Vp + (size_t)(sl * 32 + vr) * NN + vc8 * 8, vhi0, vlo0);
        split8(Vp + (size_t)(sl * 32 + vr + 16) * NN + vc8 * 8, vhi1, vlo1);
    };
    auto storeV3 = [&](int buf) {
        char* bb = sm + AT_B0 + buf * AT_BUF_B;
        *(uint4*)(bb + v_so) = vhi0;
        *(uint4*)(bb + 16896 + v_so) = vlo0;
        *(uint4*)(bb + 8448 + v_so) = vhi1;
        *(uint4*)(bb + 16896 + 8448 + v_so) = vlo1;
    };

    for (;;) {
        if (tid == 0) s_tile = atomicAdd(&g_ctr_a, 1u);
        __syncthreads();
        unsigned t = s_tile;
        if (t >= AT_TILES) break;
        int ch = 15 - (int)(t / 24);           // heavy chunks first, globally
        int bh = (int)(t % 24);
        t0 = ch * CC;
        Qp = Q + (size_t)(bh * TT + t0) * NN;
        Kp = K + (size_t)(bh * TT + t0) * NN;
        Vp = V + (size_t)(bh * TT + t0) * NN;
        Sh = g_Sh + (size_t)(bh * NCH + ch) * (NN * NN);
        Sl = g_Sl + (size_t)(bh * NCH + ch) * (NN * NN);

        // ======== Stage 1: P = QR @ KR^T, lower-triangle tiles only ============
        float acc1[2][4][4];
#pragma unroll
        for (int a = 0; a < 2; a++)
#pragma unroll
            for (int b = 0; b < 4; b++)
#pragma unroll
                for (int c = 0; c < 4; c++) acc1[a][b][c] = 0.f;

        loadQK(0);
        storeQK(0);
        __syncthreads();
        for (int sl = 0; sl < 8; sl++) {
            if (ch > 0) {
                if (sl == 6) { cpS(2, 6); CP_COMMIT(); }      // S s(0)=slab6 -> buf2 (idle)
                if (sl == 7) { cpS(0, 7); CP_COMMIT(); }      // S s(1)=slab7 -> buf0 (K6 dead)
            }
            if (sl < 7) loadQK(sl + 1);
            if (act1) {
                uint32_t ab = sb + (sl & 1) * AT_BUF_A;
                uint32_t bb = sb + AT_B0 + (sl & 1) * AT_BUF_B;
#pragma unroll
                for (int k0 = 0; k0 < 32; k0 += 16) {
                    uint32_t ah[2][4], al[2][4];
#pragma unroll
                    for (int mt = 0; mt < 2; mt++) {
                        uint32_t off = (uint32_t)(((pr * 32 + mt * 16 + lm16) * 40 +
                                                   k0 + 8 * l16) * 2);
                        ldsm4(ah[mt], ab + off);
                        ldsm4(al[mt], ab + 10240 + off);
                    }
#pragma unroll
                    for (int np = 0; np < 2; np++) {
                        uint32_t bh2[4], bl2[4];
                        uint32_t off = (uint32_t)(((pc * 32 + np * 16 + lmod8 + 8 * l16) * 40 +
                                                   k0 + 8 * l8) * 2);
                        ldsm4(bh2, bb + off);
                        ldsm4(bl2, bb + 16896 + off);
#pragma unroll
                        for (int mt = 0; mt < 2; mt++) {
                            mma_bf16(acc1[mt][2*np],   ah[mt], bh2);
                            mma_bf16(acc1[mt][2*np],   ah[mt], bl2);
                            mma_bf16(acc1[mt][2*np],   al[mt], bh2);
                            mma_bf16(acc1[mt][2*np+1], ah[mt], bh2 + 2);
                            mma_bf16(acc1[mt][2*np+1], ah[mt], bl2 + 2);
                            mma_bf16(acc1[mt][2*np+1], al[mt], bh2 + 2);
                        }
                    }
                }
            }
            if (sl < 7) { storeQK((sl + 1) & 1); __syncthreads(); }
        }
        __syncthreads();                       // sl=7 MMAs done
        if (ch == 0) loadV3(0);                // light path: prefetch stage-3 V now

        // mask (strict lower triangle) + bf16 split into smem P
        if (act1) {
#pragma unroll
            for (int mt = 0; mt < 2; mt++)
#pragma unroll
                for (int nt = 0; nt < 4; nt++)
#pragma unroll
                    for (int h = 0; h < 2; h++) {
                        int rr = pr * 32 + mt * 16 + lq + 8 * h;
                        int cn = pc * 32 + nt * 8 + lr2;
                        float v0 = (cn     < rr) ? acc1[mt][nt][2*h]   : 0.f;
                        float v1 = (cn + 1 < rr) ? acc1[mt][nt][2*h+1] : 0.f;
                        uint32_t hbits, lbits;
                        split2(v0, v1, hbits, lbits);
                        uint32_t bo = (uint32_t)((rr * 136 + cn) * 2);
                        *(uint32_t*)(sm + AT_PH + bo) = hbits;
                        *(uint32_t*)(sm + AT_PL + bo) = lbits;
                    }
        }
        if (ch > 0) CP_WAIT1();                // S s(0) complete, s(1) in flight
        __syncthreads();

        // ======== Stage 2: D = QR @ S_pref, slabs {6,7,0..5}, S triple-buffer ==
        float acc[2][8][4];
#pragma unroll
        for (int a = 0; a < 2; a++)
#pragma unroll
            for (int b = 0; b < 8; b++)
#pragma unroll
                for (int c = 0; c < 4; c++) acc[a][b][c] = 0.f;

        if (ch > 0) {
            for (int i = 0; i < 8; i++) {
                if (i < 6) { cpS((i + 1) % 3, i); CP_COMMIT(); }   // slab i for iter i+2
                if (i >= 1 && i < 7) loadQ2(i - 1);                // Q slab for iter i+1
                if (i == 7) loadV3(0);                              // prefetch stage-3 V
                uint32_t ab = sb + (i & 1) * AT_BUF_A;
                uint32_t bb = sb + AT_B0 + ((2 + i) % 3) * AT_BUF_B;
#pragma unroll
                for (int k0 = 0; k0 < 32; k0 += 16) {
                    uint32_t ah[2][4], al[2][4];
#pragma unroll
                    for (int mt = 0; mt < 2; mt++) {
                        uint32_t off = (uint32_t)(((wm * 32 + mt * 16 + lm16) * 40 +
                                                   k0 + 8 * l16) * 2);
                        ldsm4(ah[mt], ab + off);
                        ldsm4(al[mt], ab + 10240 + off);
                    }
#pragma unroll
                    for (int np = 0; np < 4; np++) {
                        uint32_t bh2[4], bl2[4];
                        uint32_t off = (uint32_t)(((k0 + lmod8 + 8 * l8) * 264 +
                                                   wn * 64 + np * 16 + 8 * l16) * 2);
                        ldsm4t(bh2, bb + off);
                        ldsm4t(bl2, bb + 16896 + off);
#pragma unroll
                        for (int mt = 0; mt < 2; mt++) {
                            mma_bf16(acc[mt][2*np],   ah[mt], bh2);
                            mma_bf16(acc[mt][2*np],   ah[mt], bl2);
                            mma_bf16(acc[mt][2*np],   al[mt], bh2);
                            mma_bf16(acc[mt][2*np+1], ah[mt], bh2 + 2);
                            mma_bf16(acc[mt][2*np+1], ah[mt], bl2 + 2);
                            mma_bf16(acc[mt][2*np+1], al[mt], bh2 + 2);
                        }
                    }
                }
                if (i < 7) {
                    if (i >= 1) storeQ2((i + 1) & 1);
                    if (i < 6) CP_WAIT1(); else CP_WAIT0();
                    __syncthreads();
                }
            }
            __syncthreads();                   // i=7 MMAs done before V reuses buf0
        }

        // ======== Stage 3: D += P @ V — skip slabs above warp's diagonal =======
        storeV3(0);
        __syncthreads();
        for (int sl = 0; sl < 4; sl++) {
            if (sl < 3) loadV3(sl + 1);
            if (sl <= wm) {
                int s0 = sl * 32;
                uint32_t bb = sb + AT_B0 + (sl & 1) * AT_BUF_B;
#pragma unroll
                for (int k0 = 0; k0 < 32; k0 += 16) {
                    uint32_t ah[2][4], al[2][4];
#pragma unroll
                    for (int mt = 0; mt < 2; mt++) {
                        uint32_t off = (uint32_t)(((wm * 32 + mt * 16 + lm16) * 136 +
                                                   s0 + k0 + 8 * l16) * 2);
                        ldsm4(ah[mt], sb + AT_PH + off);
                        ldsm4(al[mt], sb + AT_PL + off);
                    }
#pragma unroll
                    for (int np = 0; np < 4; np++) {
                        uint32_t bh2[4], bl2[4];
                        uint32_t off = (uint32_t)(((k0 + lmod8 + 8 * l8) * 264 +
                                                   wn * 64 + np * 16 + 8 * l16) * 2);
                        ldsm4t(bh2, bb + off);
                        ldsm4t(bl2, bb + 16896 + off);
#pragma unroll
                        for (int mt = 0; mt < 2; mt++) {
                            mma_bf16(acc[mt][2*np],   ah[mt], bh2);
                            mma_bf16(acc[mt][2*np],   ah[mt], bl2);
                            mma_bf16(acc[mt][2*np],   al[mt], bh2);
                            mma_bf16(acc[mt][2*np+1], ah[mt], bh2 + 2);
                            mma_bf16(acc[mt][2*np+1], ah[mt], bl2 + 2);
                            mma_bf16(acc[mt][2*np+1], al[mt], bh2 + 2);
                        }
                    }
                }
            }
            if (sl < 3) { storeV3((sl + 1) & 1); __syncthreads(); }
        }

        // epilogue
#pragma unroll
        for (int mt = 0; mt < 2; mt++)
#pragma unroll
            for (int nt = 0; nt < 8; nt++)
#pragma unroll
                for (int h = 0; h < 2; h++) {
                    int rr = wm * 32 + mt * 16 + lq + 8 * h;
                    int cc = wn * 64 + nt * 8 + lr2;
                    float2 o; o.x = acc[mt][nt][2*h]; o.y = acc[mt][nt][2*h+1];
                    *(float2*)(out + (size_t)(bh * TT + t0 + rr) * NN + cc) = o;
                }
        // next tile's grab-sync orders smem reuse
    }
}

// ---------------- launcher -------------------------------------------------------
extern "C" void kernel_launch(void* const* d_in, const int* in_sizes, int n_in,
                              void* d_out, int out_size) {
    const float* Q = (const float*)d_in[0];
    const float* K = (const float*)d_in[1];
    const float* V = (const float*)d_in[2];
    float* out = (float*)d_out;

    static bool attr_set = false;
    static int nsm = 148;
    if (!attr_set) {
        cudaFuncSetAttribute(k_kv,   cudaFuncAttributeMaxDynamicSharedMemorySize, SMEM_KV);
        cudaFuncSetAttribute(k_attn, cudaFuncAttributeMaxDynamicSharedMemorySize, SMEM_ATTN);
        cudaDeviceGetAttribute(&nsm, cudaDevAttrMultiProcessorCount, 0);
        attr_set = true;
    }

    k_tables<<<512, 512>>>();
    int gkv = nsm < KV_TILES ? nsm : KV_TILES;
    int gat = nsm < AT_TILES ? nsm : AT_TILES;
    k_kv<<<gkv, 512, SMEM_KV>>>(K, V);
    k_scan<<<(BH * NN * NN / 4 + 255) / 256, 256>>>();
    k_attn<<<gat, 512, SMEM_ATTN>>>(Q, K, V, out);
}

// round 12
// speedup vs baseline: 1.3008x; 1.3008x over previous
#include <cuda_runtime.h>
#include <cuda_fp16.h>
#include <math.h>
#include <stdint.h>

#define BH   24
#define TT   2048
#define NN   256
#define CC   128
#define NCH  16

// ---------------- device scratch ----------------------------------------------
__device__ float g_tabc[TT * (NN/2)];
__device__ float g_tabs[TT * (NN/2)];
__device__ float g_S[BH*NCH*NN*NN];
__device__ __half g_Sh[BH*NCH*NN*NN];          // S_pref, fp16 (B operand: single)

// ---------------- PTX helpers ---------------------------------------------------
__device__ __forceinline__ uint32_t smem_u32(const void* p) {
    uint32_t a;
    asm("{ .reg .u64 t; cvta.to.shared.u64 t, %1; cvt.u32.u64 %0, t; }" : "=r"(a) : "l"(p));
    return a;
}
__device__ __forceinline__ void cpa16(uint32_t s, const void* g) {
    asm volatile("cp.async.cg.shared.global [%0], [%1], 16;" :: "r"(s), "l"(g));
}
#define CP_COMMIT() asm volatile("cp.async.commit_group;" ::: "memory")
#define CP_WAIT0()  asm volatile("cp.async.wait_group 0;" ::: "memory")

__device__ __forceinline__ void ldsm4(uint32_t* r, uint32_t a) {
    asm volatile("ldmatrix.sync.aligned.m8n8.x4.shared.b16 {%0,%1,%2,%3}, [%4];"
        : "=r"(r[0]), "=r"(r[1]), "=r"(r[2]), "=r"(r[3]) : "r"(a));
}
__device__ __forceinline__ void ldsm4t(uint32_t* r, uint32_t a) {
    asm volatile("ldmatrix.sync.aligned.m8n8.x4.trans.shared.b16 {%0,%1,%2,%3}, [%4];"
        : "=r"(r[0]), "=r"(r[1]), "=r"(r[2]), "=r"(r[3]) : "r"(a));
}
__device__ __forceinline__ void mma_f16(float* d, const uint32_t* a, const uint32_t* b) {
    asm volatile("mma.sync.aligned.m16n8k16.row.col.f32.f16.f16.f32 "
        "{%0,%1,%2,%3}, {%4,%5,%6,%7}, {%8,%9}, {%0,%1,%2,%3};"
        : "+f"(d[0]), "+f"(d[1]), "+f"(d[2]), "+f"(d[3])
        : "r"(a[0]), "r"(a[1]), "r"(a[2]), "r"(a[3]), "r"(b[0]), "r"(b[1]));
}

// ---------------- fp16 split / cvt helpers --------------------------------------
__device__ __forceinline__ void splitH2(float x, float y, uint32_t& h, uint32_t& l) {
    __half2 H = __floats2half2_rn(x, y);
    float2 hf = __half22float2(H);
    __half2 L = __floats2half2_rn(x - hf.x, y - hf.y);
    h = *(uint32_t*)&H; l = *(uint32_t*)&L;
}
__device__ __forceinline__ uint32_t cvtH2(float x, float y) {
    __half2 H = __floats2half2_rn(x, y);
    return *(uint32_t*)&H;
}
// A-operand: rope + hi/lo split of 8 consecutive features
__device__ __forceinline__ void rope_split8_cs(const float* __restrict__ src,
                                               float4 c, float4 s,
                                               uint4& hi, uint4& lo) {
    float4 a = *(const float4*)(src);
    float4 b = *(const float4*)(src + 4);
    float r0 = a.x*c.x - a.y*s.x, r1 = a.y*c.x + a.x*s.x;
    float r2 = a.z*c.y - a.w*s.y, r3 = a.w*c.y + a.z*s.y;
    float r4 = b.x*c.z - b.y*s.z, r5 = b.y*c.z + b.x*s.z;
    float r6 = b.z*c.w - b.w*s.w, r7 = b.w*c.w + b.z*s.w;
    splitH2(r0, r1, hi.x, lo.x); splitH2(r2, r3, hi.y, lo.y);
    splitH2(r4, r5, hi.z, lo.z); splitH2(r6, r7, hi.w, lo.w);
}
__device__ __forceinline__ void rope_split8(const float* __restrict__ src, int t, int f,
                                            uint4& hi, uint4& lo) {
    float4 c = *(const float4*)(g_tabc + t * 128 + (f >> 1));
    float4 s = *(const float4*)(g_tabs + t * 128 + (f >> 1));
    rope_split8_cs(src, c, s, hi, lo);
}
// B-operand: rope + single fp16
__device__ __forceinline__ uint4 rope_cvt8_cs(const float* __restrict__ src,
                                              float4 c, float4 s) {
    float4 a = *(const float4*)(src);
    float4 b = *(const float4*)(src + 4);
    uint4 h;
    h.x = cvtH2(a.x*c.x - a.y*s.x, a.y*c.x + a.x*s.x);
    h.y = cvtH2(a.z*c.y - a.w*s.y, a.w*c.y + a.z*s.y);
    h.z = cvtH2(b.x*c.z - b.y*s.z, b.y*c.z + b.x*s.z);
    h.w = cvtH2(b.z*c.w - b.w*s.w, b.w*c.w + b.z*s.w);
    return h;
}
// B-operand: plain single fp16
__device__ __forceinline__ uint4 cvt8(const float* __restrict__ src) {
    float4 a = *(const float4*)(src);
    float4 b = *(const float4*)(src + 4);
    uint4 h;
    h.x = cvtH2(a.x, a.y); h.y = cvtH2(a.z, a.w);
    h.z = cvtH2(b.x, b.y); h.w = cvtH2(b.z, b.w);
    return h;
}

// ---------------- kernel 1: RoPE phase tables -----------------------------------
__global__ void k_tables() {
    int id = blockIdx.x * blockDim.x + threadIdx.x;
    if (id >= TT * (NN/2)) return;
    int t = id >> 7;
    int j = id & 127;
    double fr_d = exp2(-(double)j / 8.0) / (2.0 * 3.14159265358979323846);
    float f32 = (float)fr_d;
    float ph  = (float)t * f32;
    ph = ph - floorf(ph);
    float ang = ph * 6.28318530717958647692f;
    double angd = (double)ang;
    g_tabc[id] = (float)cos(angd);
    g_tabs[id] = (float)sin(angd);
}

// ---------------- kernel 2: chunk KV state S_ch = KR^T @ V (fused rope) ---------
#define KV_BUF_A 17408
#define KV_B0    34816
#define KV_BUF_B 16896
#define SMEM_KV  68608

__global__ void __launch_bounds__(512, 1) k_kv(const float* __restrict__ K,
                                               const float* __restrict__ V) {
    extern __shared__ char sm[];
    uint32_t sb = smem_u32(sm);
    int tid = threadIdx.x, lane = tid & 31, wid = tid >> 5;
    int wm = wid >> 2, wn = wid & 3;
    int bx = blockIdx.x;
    int bh = bx / 15, ch = bx % 15;
    int m0g = blockIdx.y * 128;
    int t0 = ch * CC;
    int l16 = lane >> 4, lmod8 = lane & 7, l8 = (lane >> 3) & 1;
    int lq = lane >> 2, lr2 = (lane & 3) * 2;

    const float* Kp = K + (size_t)(bh * TT + t0) * NN;
    const float* Vp = V + (size_t)(bh * TT + t0) * NN;

    int ar = tid >> 4, ac8 = tid & 15;
    uint32_t a_so = (uint32_t)(ar * 272 + ac8 * 16);
    int vr = tid >> 5, vc8 = tid & 31;
    uint32_t v_so = (uint32_t)(vr * 528 + vc8 * 16);

    uint4 ahi, alo, vh0, vh1;
    auto loadSlab = [&](int sl) {
        int tk = t0 + sl * 32 + ar;
        rope_split8(Kp + (size_t)(sl * 32 + ar) * NN + m0g + ac8 * 8,
                    tk, m0g + ac8 * 8, ahi, alo);
        vh0 = cvt8(Vp + (size_t)(sl * 32 + vr) * NN + vc8 * 8);
        vh1 = cvt8(Vp + (size_t)(sl * 32 + vr + 16) * NN + vc8 * 8);
    };
    auto storeSlab = [&](int buf) {
        char* ab = sm + buf * KV_BUF_A;
        *(uint4*)(ab + a_so) = ahi;
        *(uint4*)(ab + 8704 + a_so) = alo;
        char* bb = sm + KV_B0 + buf * KV_BUF_B;
        *(uint4*)(bb + v_so) = vh0;
        *(uint4*)(bb + 8448 + v_so) = vh1;
    };

    float acc[2][8][4];
#pragma unroll
    for (int a = 0; a < 2; a++)
#pragma unroll
        for (int b = 0; b < 8; b++)
#pragma unroll
            for (int c = 0; c < 4; c++) acc[a][b][c] = 0.f;

    loadSlab(0);
    storeSlab(0);
    __syncthreads();
    for (int sl = 0; sl < 4; sl++) {
        if (sl < 3) loadSlab(sl + 1);
        uint32_t ab = sb + (sl & 1) * KV_BUF_A;
        uint32_t bb = sb + KV_B0 + (sl & 1) * KV_BUF_B;
#pragma unroll
        for (int k0 = 0; k0 < 32; k0 += 16) {
            uint32_t ah[2][4], al[2][4];
#pragma unroll
            for (int mt = 0; mt < 2; mt++) {
                uint32_t off = (uint32_t)(((k0 + lmod8 + 8 * l16) * 136 +
                                           wm * 32 + mt * 16 + 8 * l8) * 2);
                ldsm4t(ah[mt], ab + off);
                ldsm4t(al[mt], ab + 8704 + off);
            }
#pragma unroll
            for (int np = 0; np < 4; np++) {
                uint32_t bh2[4];
                uint32_t off = (uint32_t)(((k0 + lmod8 + 8 * l8) * 264 +
                                           wn * 64 + np * 16 + 8 * l16) * 2);
                ldsm4t(bh2, bb + off);
#pragma unroll
                for (int mt = 0; mt < 2; mt++) {
                    mma_f16(acc[mt][2*np],   ah[mt], bh2);
                    mma_f16(acc[mt][2*np],   al[mt], bh2);
                    mma_f16(acc[mt][2*np+1], ah[mt], bh2 + 2);
                    mma_f16(acc[mt][2*np+1], al[mt], bh2 + 2);
                }
            }
        }
        if (sl < 3) { storeSlab((sl + 1) & 1); __syncthreads(); }
    }
    float* Sp = g_S + (size_t)(bh * NCH + ch) * (NN * NN);
#pragma unroll
    for (int mt = 0; mt < 2; mt++)
#pragma unroll
        for (int nt = 0; nt < 8; nt++)
#pragma unroll
            for (int h = 0; h < 2; h++) {
                int rr = m0g + wm * 32 + mt * 16 + lq + 8 * h;
                int cc = wn * 64 + nt * 8 + lr2;
                float2 o; o.x = acc[mt][nt][2*h]; o.y = acc[mt][nt][2*h+1];
                *(float2*)(Sp + (size_t)rr * NN + cc) = o;
            }
}

// ---------------- kernel 3: exclusive prefix scan + fp16 cvt (MLP) --------------
__global__ void k_scan() {
    int g = blockIdx.x * blockDim.x + threadIdx.x;
    if (g >= BH * NN * NN / 4) return;
    int bh = g >> 14;
    int e4 = (g & 16383) << 2;
    size_t base = (size_t)bh * NCH * (NN * NN) + e4;
    float4 vals[NCH - 1];
#pragma unroll
    for (int i = 0; i < NCH - 1; i++)
        vals[i] = *(const float4*)(g_S + base + (size_t)i * (NN * NN));
    float r0 = 0.f, r1 = 0.f, r2 = 0.f, r3 = 0.f;
#pragma unroll
    for (int i = 0; i < NCH; i++) {
        size_t p = base + (size_t)i * (NN * NN);
        uint2 H;
        H.x = cvtH2(r0, r1);
        H.y = cvtH2(r2, r3);
        *(uint2*)(g_Sh + p) = H;
        if (i < NCH - 1) { r0 += vals[i].x; r1 += vals[i].y; r2 += vals[i].z; r3 += vals[i].w; }
    }
}

// ---------------- kernel 4: Out = QR@S_pref + strict_tril(QR@KR^T)@V ------------
#define AT_BUF_A 20480
#define AT_B0    40960
#define AT_BUF_B 16896
#define AT_PH    74752
#define AT_PL    109568
#define SMEM_ATTN 144384

// stage-1 warp->tile LUT (10 live lower-triangle tiles, 3/3/2/2 per SMSP)
#define S1_R_PACK 981476u
#define S1_C_PACK 54436u

__global__ void __launch_bounds__(512, 1) k_attn(const float* __restrict__ Q,
                                                 const float* __restrict__ K,
                                                 const float* __restrict__ V,
                                                 float* __restrict__ out) {
    extern __shared__ char sm[];
    uint32_t sb = smem_u32(sm);
    int tid = threadIdx.x, lane = tid & 31, wid = tid >> 5;
    int wm = wid >> 2, wn = wid & 3;
    int bh = blockIdx.x >> 4, ch = 15 - (blockIdx.x & 15);
    int t0 = ch * CC;
    int lm16 = lane & 15, l16 = lane >> 4, lmod8 = lane & 7, l8 = (lane >> 3) & 1;
    int lq = lane >> 2, lr2 = (lane & 3) * 2;

    const float* Qp = Q + (size_t)(bh * TT + t0) * NN;
    const float* Kp = K + (size_t)(bh * TT + t0) * NN;
    const float* Vp = V + (size_t)(bh * TT + t0) * NN;
    const __half* Sh = g_Sh + (size_t)(bh * NCH + ch) * (NN * NN);

    int sr = tid >> 2, sc8 = tid & 3;
    uint32_t s_so = (uint32_t)(sr * 80 + sc8 * 16);
    int vr = tid >> 5, vc8 = tid & 31;
    uint32_t v_so = (uint32_t)(vr * 528 + vc8 * 16);

    // ---- staging lambdas -----------------------------------------------------
    uint4 qhi, qlo, khi;
    auto loadQK = [&](int sl) {
        int f = sl * 32 + sc8 * 8;
        float4 c = *(const float4*)(g_tabc + (t0 + sr) * 128 + (f >> 1));
        float4 s = *(const float4*)(g_tabs + (t0 + sr) * 128 + (f >> 1));
        rope_split8_cs(Qp + (size_t)sr * NN + f, c, s, qhi, qlo);
        khi = rope_cvt8_cs(Kp + (size_t)sr * NN + f, c, s);
    };
    auto storeQK = [&](int buf) {
        char* ab = sm + buf * AT_BUF_A;
        *(uint4*)(ab + s_so) = qhi;
        *(uint4*)(ab + 10240 + s_so) = qlo;
        char* bb = sm + AT_B0 + buf * AT_BUF_B;
        *(uint4*)(bb + s_so) = khi;
    };
    auto loadQ2 = [&](int sl) {
        int f = sl * 32 + sc8 * 8;
        float4 c = *(const float4*)(g_tabc + (t0 + sr) * 128 + (f >> 1));
        float4 s = *(const float4*)(g_tabs + (t0 + sr) * 128 + (f >> 1));
        rope_split8_cs(Qp + (size_t)sr * NN + f, c, s, qhi, qlo);
    };
    auto storeQ2 = [&](int buf) {
        char* ab = sm + buf * AT_BUF_A;
        *(uint4*)(ab + s_so) = qhi;
        *(uint4*)(ab + 10240 + s_so) = qlo;
    };
    auto cpS = [&](int buf, int sl) {
        uint32_t bb = sb + AT_B0 + buf * AT_BUF_B;
        int f0 = sl * 32;
#pragma unroll
        for (int v = tid; v < 1024; v += 512) {
            int r = v >> 5, c8 = v & 31;
            uint32_t so = (uint32_t)(r * 528 + c8 * 16);
            cpa16(bb + so, Sh + (size_t)(f0 + r) * NN + c8 * 8);
        }
    };
    uint4 vh0, vh1;
    auto loadV3 = [&](int sl) {
        vh0 = cvt8(Vp + (size_t)(sl * 32 + vr) * NN + vc8 * 8);
        vh1 = cvt8(Vp + (size_t)(sl * 32 + vr + 16) * NN + vc8 * 8);
    };
    auto storeV3 = [&](int buf) {
        char* bb = sm + AT_B0 + buf * AT_BUF_B;
        *(uint4*)(bb + v_so) = vh0;
        *(uint4*)(bb + 8448 + v_so) = vh1;
    };

    int pr = (S1_R_PACK >> (wid * 2)) & 3;
    int pc = (S1_C_PACK >> (wid * 2)) & 3;
    bool act1 = (wid < 10);

    // ======== Stage 1: P = QR @ KR^T, lower-triangle tiles only ================
    float acc1[2][4][4];
#pragma unroll
    for (int a = 0; a < 2; a++)
#pragma unroll
        for (int b = 0; b < 4; b++)
#pragma unroll
            for (int c = 0; c < 4; c++) acc1[a][b][c] = 0.f;

    loadQK(0);
    storeQK(0);
    __syncthreads();
    for (int sl = 0; sl < 8; sl++) {
        if (sl < 7) loadQK(sl + 1);
        else if (ch > 0) { cpS(0, 6); CP_COMMIT(); }   // S slab 6 -> buf0 (K buf0 dead)
        if (act1) {
            uint32_t ab = sb + (sl & 1) * AT_BUF_A;
            uint32_t bb = sb + AT_B0 + (sl & 1) * AT_BUF_B;
#pragma unroll
            for (int k0 = 0; k0 < 32; k0 += 16) {
                uint32_t ah[2][4], al[2][4];
#pragma unroll
                for (int mt = 0; mt < 2; mt++) {
                    uint32_t off = (uint32_t)(((pr * 32 + mt * 16 + lm16) * 40 +
                                               k0 + 8 * l16) * 2);
                    ldsm4(ah[mt], ab + off);
                    ldsm4(al[mt], ab + 10240 + off);
                }
#pragma unroll
                for (int np = 0; np < 2; np++) {
                    uint32_t bh2[4];
                    uint32_t off = (uint32_t)(((pc * 32 + np * 16 + lmod8 + 8 * l16) * 40 +
                                               k0 + 8 * l8) * 2);
                    ldsm4(bh2, bb + off);
#pragma unroll
                    for (int mt = 0; mt < 2; mt++) {
                        mma_f16(acc1[mt][2*np],   ah[mt], bh2);
                        mma_f16(acc1[mt][2*np],   al[mt], bh2);
                        mma_f16(acc1[mt][2*np+1], ah[mt], bh2 + 2);
                        mma_f16(acc1[mt][2*np+1], al[mt], bh2 + 2);
                    }
                }
            }
        }
        if (sl < 7) { storeQK((sl + 1) & 1); __syncthreads(); }
    }
    __syncthreads();                       // all sl=7 MMAs done (K buf1 free)
    if (ch > 0) { cpS(1, 7); CP_COMMIT(); }   // S slab 7 -> buf1, overlaps P writes
    else loadV3(0);                           // ch=0: prefetch stage-3 V

    // mask (strict lower triangle) + fp16 split into smem P (live tiles only)
    if (act1) {
#pragma unroll
        for (int mt = 0; mt < 2; mt++)
#pragma unroll
            for (int nt = 0; nt < 4; nt++)
#pragma unroll
                for (int h = 0; h < 2; h++) {
                    int rr = pr * 32 + mt * 16 + lq + 8 * h;
                    int cn = pc * 32 + nt * 8 + lr2;
                    float v0 = (cn     < rr) ? acc1[mt][nt][2*h]   : 0.f;
                    float v1 = (cn + 1 < rr) ? acc1[mt][nt][2*h+1] : 0.f;
                    uint32_t hbits, lbits;
                    splitH2(v0, v1, hbits, lbits);
                    uint32_t bo = (uint32_t)((rr * 136 + cn) * 2);
                    *(uint32_t*)(sm + AT_PH + bo) = hbits;
                    *(uint32_t*)(sm + AT_PL + bo) = lbits;
                }
    }
    if (ch > 0) CP_WAIT0();
    __syncthreads();

    // ======== Stage 2: D = QR @ S_pref, slab order {6,7,0..5} ==================
    float acc[2][8][4];
#pragma unroll
    for (int a = 0; a < 2; a++)
#pragma unroll
        for (int b = 0; b < 8; b++)
#pragma unroll
            for (int c = 0; c < 4; c++) acc[a][b][c] = 0.f;

    if (ch > 0) {
        for (int i = 0; i < 8; i++) {
            if (i >= 1 && i < 7) {
                int sn = (7 + i) & 7;               // next slab
                loadQ2(sn);
                cpS((i + 1) & 1, sn);
                CP_COMMIT();
            } else if (i == 7) loadV3(0);           // prefetch stage-3 V slab 0
            uint32_t ab = sb + (i & 1) * AT_BUF_A;
            uint32_t bb = sb + AT_B0 + (i & 1) * AT_BUF_B;
#pragma unroll
            for (int k0 = 0; k0 < 32; k0 += 16) {
                uint32_t ah[2][4], al[2][4];
#pragma unroll
                for (int mt = 0; mt < 2; mt++) {
                    uint32_t off = (uint32_t)(((wm * 32 + mt * 16 + lm16) * 40 +
                                               k0 + 8 * l16) * 2);
                    ldsm4(ah[mt], ab + off);
                    ldsm4(al[mt], ab + 10240 + off);
                }
#pragma unroll
                for (int np = 0; np < 4; np++) {
                    uint32_t bh2[4];
                    uint32_t off = (uint32_t)(((k0 + lmod8 + 8 * l8) * 264 +
                                               wn * 64 + np * 16 + 8 * l16) * 2);
                    ldsm4t(bh2, bb + off);
#pragma unroll
                    for (int mt = 0; mt < 2; mt++) {
                        mma_f16(acc[mt][2*np],   ah[mt], bh2);
                        mma_f16(acc[mt][2*np],   al[mt], bh2);
                        mma_f16(acc[mt][2*np+1], ah[mt], bh2 + 2);
                        mma_f16(acc[mt][2*np+1], al[mt], bh2 + 2);
                    }
                }
            }
            if (i < 7) {
                if (i >= 1) storeQ2((i + 1) & 1);
                CP_WAIT0();
                __syncthreads();
            }
        }
    }

    // ======== Stage 3: D += P @ V — skip slabs above warp's diagonal ===========
    storeV3(0);                            // buf0 free (last read at i=6 / ch=0: stage1 sl=6)
    __syncthreads();
    for (int sl = 0; sl < 4; sl++) {
        if (sl < 3) loadV3(sl + 1);
        if (sl <= wm) {
            int s0 = sl * 32;
            uint32_t bb = sb + AT_B0 + (sl & 1) * AT_BUF_B;
#pragma unroll
            for (int k0 = 0; k0 < 32; k0 += 16) {
                uint32_t ah[2][4], al[2][4];
#pragma unroll
                for (int mt = 0; mt < 2; mt++) {
                    uint32_t off = (uint32_t)(((wm * 32 + mt * 16 + lm16) * 136 +
                                               s0 + k0 + 8 * l16) * 2);
                    ldsm4(ah[mt], sb + AT_PH + off);
                    ldsm4(al[mt], sb + AT_PL + off);
                }
#pragma unroll
                for (int np = 0; np < 4; np++) {
                    uint32_t bh2[4];
                    uint32_t off = (uint32_t)(((k0 + lmod8 + 8 * l8) * 264 +
                                               wn * 64 + np * 16 + 8 * l16) * 2);
                    ldsm4t(bh2, bb + off);
#pragma unroll
                    for (int mt = 0; mt < 2; mt++) {
                        mma_f16(acc[mt][2*np],   ah[mt], bh2);
                        mma_f16(acc[mt][2*np],   al[mt], bh2);
                        mma_f16(acc[mt][2*np+1], ah[mt], bh2 + 2);
                        mma_f16(acc[mt][2*np+1], al[mt], bh2 + 2);
                    }
                }
            }
        }
        if (sl < 3) { storeV3((sl + 1) & 1); __syncthreads(); }
    }

    // epilogue
#pragma unroll
    for (int mt = 0; mt < 2; mt++)
#pragma unroll
        for (int nt = 0; nt < 8; nt++)
#pragma unroll
            for (int h = 0; h < 2; h++) {
                int rr = wm * 32 + mt * 16 + lq + 8 * h;
                int cc = wn * 64 + nt * 8 + lr2;
                float2 o; o.x = acc[mt][nt][2*h]; o.y = acc[mt][nt][2*h+1];
                *(float2*)(out + (size_t)(bh * TT + t0 + rr) * NN + cc) = o;
            }
}

// ---------------- launcher -------------------------------------------------------
extern "C" void kernel_launch(void* const* d_in, const int* in_sizes, int n_in,
                              void* d_out, int out_size) {
    const float* Q = (const float*)d_in[0];
    const float* K = (const float*)d_in[1];
    const float* V = (const float*)d_in[2];
    float* out = (float*)d_out;

    static bool attr_set = false;
    if (!attr_set) {
        cudaFuncSetAttribute(k_kv,   cudaFuncAttributeMaxDynamicSharedMemorySize, SMEM_KV);
        cudaFuncSetAttribute(k_attn, cudaFuncAttributeMaxDynamicSharedMemorySize, SMEM_ATTN);
        attr_set = true;
    }

    k_tables<<<512, 512>>>();
    k_kv<<<dim3(BH * (NCH - 1), 2), 512, SMEM_KV>>>(K, V);
    k_scan<<<(BH * NN * NN / 4 + 255) / 256, 256>>>();
    k_attn<<<BH * NCH, 512, SMEM_ATTN>>>(Q, K, V, out);
}

// round 13
// speedup vs baseline: 1.4988x; 1.1522x over previous
#include <cuda_runtime.h>
#include <cuda_fp16.h>
#include <math.h>
#include <stdint.h>

#define BH   24
#define TT   2048
#define NN   256
#define CC   128
#define NCH  16

// ---------------- device scratch ----------------------------------------------
__device__ float g_tabc[TT * (NN/2)];
__device__ float g_tabs[TT * (NN/2)];
__device__ float g_S[BH*NCH*NN*NN];
__device__ __half g_Sh[BH*NCH*NN*NN];          // S_pref, fp16

// ---------------- PTX helpers ---------------------------------------------------
__device__ __forceinline__ uint32_t smem_u32(const void* p) {
    uint32_t a;
    asm("{ .reg .u64 t; cvta.to.shared.u64 t, %1; cvt.u32.u64 %0, t; }" : "=r"(a) : "l"(p));
    return a;
}
__device__ __forceinline__ void cpa16(uint32_t s, const void* g) {
    asm volatile("cp.async.cg.shared.global [%0], [%1], 16;" :: "r"(s), "l"(g));
}
#define CP_COMMIT() asm volatile("cp.async.commit_group;" ::: "memory")
#define CP_WAIT0()  asm volatile("cp.async.wait_group 0;" ::: "memory")

__device__ __forceinline__ void ldsm4(uint32_t* r, uint32_t a) {
    asm volatile("ldmatrix.sync.aligned.m8n8.x4.shared.b16 {%0,%1,%2,%3}, [%4];"
        : "=r"(r[0]), "=r"(r[1]), "=r"(r[2]), "=r"(r[3]) : "r"(a));
}
__device__ __forceinline__ void ldsm4t(uint32_t* r, uint32_t a) {
    asm volatile("ldmatrix.sync.aligned.m8n8.x4.trans.shared.b16 {%0,%1,%2,%3}, [%4];"
        : "=r"(r[0]), "=r"(r[1]), "=r"(r[2]), "=r"(r[3]) : "r"(a));
}
__device__ __forceinline__ void mma_f16(float* d, const uint32_t* a, const uint32_t* b) {
    asm volatile("mma.sync.aligned.m16n8k16.row.col.f32.f16.f16.f32 "
        "{%0,%1,%2,%3}, {%4,%5,%6,%7}, {%8,%9}, {%0,%1,%2,%3};"
        : "+f"(d[0]), "+f"(d[1]), "+f"(d[2]), "+f"(d[3])
        : "r"(a[0]), "r"(a[1]), "r"(a[2]), "r"(a[3]), "r"(b[0]), "r"(b[1]));
}

// ---------------- fp16 cvt helpers -----------------------------------------------
__device__ __forceinline__ uint32_t cvtH2(float x, float y) {
    __half2 H = __floats2half2_rn(x, y);
    return *(uint32_t*)&H;
}
// rope + single fp16 of 8 consecutive features, preloaded cos/sin
__device__ __forceinline__ uint4 rope_cvt8_cs(const float* __restrict__ src,
                                              float4 c, float4 s) {
    float4 a = *(const float4*)(src);
    float4 b = *(const float4*)(src + 4);
    uint4 h;
    h.x = cvtH2(a.x*c.x - a.y*s.x, a.y*c.x + a.x*s.x);
    h.y = cvtH2(a.z*c.y - a.w*s.y, a.w*c.y + a.z*s.y);
    h.z = cvtH2(b.x*c.z - b.y*s.z, b.y*c.z + b.x*s.z);
    h.w = cvtH2(b.z*c.w - b.w*s.w, b.w*c.w + b.z*s.w);
    return h;
}
__device__ __forceinline__ uint4 rope_cvt8(const float* __restrict__ src, int t, int f) {
    float4 c = *(const float4*)(g_tabc + t * 128 + (f >> 1));
    float4 s = *(const float4*)(g_tabs + t * 128 + (f >> 1));
    return rope_cvt8_cs(src, c, s);
}
__device__ __forceinline__ uint4 cvt8(const float* __restrict__ src) {
    float4 a = *(const float4*)(src);
    float4 b = *(const float4*)(src + 4);
    uint4 h;
    h.x = cvtH2(a.x, a.y); h.y = cvtH2(a.z, a.w);
    h.z = cvtH2(b.x, b.y); h.w = cvtH2(b.z, b.w);
    return h;
}

// ---------------- kernel 1: RoPE phase tables -----------------------------------
__global__ void k_tables() {
    int id = blockIdx.x * blockDim.x + threadIdx.x;
    if (id >= TT * (NN/2)) return;
    int t = id >> 7;
    int j = id & 127;
    double fr_d = exp2(-(double)j / 8.0) / (2.0 * 3.14159265358979323846);
    float f32 = (float)fr_d;
    float ph  = (float)t * f32;
    ph = ph - floorf(ph);
    float ang = ph * 6.28318530717958647692f;
    double angd = (double)ang;
    g_tabc[id] = (float)cos(angd);
    g_tabs[id] = (float)sin(angd);
}

// ---------------- kernel 2: chunk KV state S_ch = KR^T @ V (fused rope) ---------
#define KV_BUF_A 8704
#define KV_B0    17408
#define KV_BUF_B 16896
#define SMEM_KV  51200

__global__ void __launch_bounds__(512, 1) k_kv(const float* __restrict__ K,
                                               const float* __restrict__ V) {
    extern __shared__ char sm[];
    uint32_t sb = smem_u32(sm);
    int tid = threadIdx.x, lane = tid & 31, wid = tid >> 5;
    int wm = wid >> 2, wn = wid & 3;
    int bx = blockIdx.x;
    int bh = bx / 15, ch = bx % 15;
    int m0g = blockIdx.y * 128;
    int t0 = ch * CC;
    int l16 = lane >> 4, lmod8 = lane & 7, l8 = (lane >> 3) & 1;
    int lq = lane >> 2, lr2 = (lane & 3) * 2;

    const float* Kp = K + (size_t)(bh * TT + t0) * NN;
    const float* Vp = V + (size_t)(bh * TT + t0) * NN;

    int ar = tid >> 4, ac8 = tid & 15;
    uint32_t a_so = (uint32_t)(ar * 272 + ac8 * 16);
    int vr = tid >> 5, vc8 = tid & 31;
    uint32_t v_so = (uint32_t)(vr * 528 + vc8 * 16);

    uint4 ah4, vh0, vh1;
    auto loadSlab = [&](int sl) {
        int tk = t0 + sl * 32 + ar;
        ah4 = rope_cvt8(Kp + (size_t)(sl * 32 + ar) * NN + m0g + ac8 * 8,
                        tk, m0g + ac8 * 8);
        vh0 = cvt8(Vp + (size_t)(sl * 32 + vr) * NN + vc8 * 8);
        vh1 = cvt8(Vp + (size_t)(sl * 32 + vr + 16) * NN + vc8 * 8);
    };
    auto storeSlab = [&](int buf) {
        char* ab = sm + buf * KV_BUF_A;
        *(uint4*)(ab + a_so) = ah4;
        char* bb = sm + KV_B0 + buf * KV_BUF_B;
        *(uint4*)(bb + v_so) = vh0;
        *(uint4*)(bb + 8448 + v_so) = vh1;
    };

    float acc[2][8][4];
#pragma unroll
    for (int a = 0; a < 2; a++)
#pragma unroll
        for (int b = 0; b < 8; b++)
#pragma unroll
            for (int c = 0; c < 4; c++) acc[a][b][c] = 0.f;

    loadSlab(0);
    storeSlab(0);
    __syncthreads();
    for (int sl = 0; sl < 4; sl++) {
        if (sl < 3) loadSlab(sl + 1);
        uint32_t ab = sb + (sl & 1) * KV_BUF_A;
        uint32_t bb = sb + KV_B0 + (sl & 1) * KV_BUF_B;
#pragma unroll
        for (int k0 = 0; k0 < 32; k0 += 16) {
            uint32_t ah[2][4];
#pragma unroll
            for (int mt = 0; mt < 2; mt++) {
                uint32_t off = (uint32_t)(((k0 + lmod8 + 8 * l16) * 136 +
                                           wm * 32 + mt * 16 + 8 * l8) * 2);
                ldsm4t(ah[mt], ab + off);
            }
#pragma unroll
            for (int np = 0; np < 4; np++) {
                uint32_t bh2[4];
                uint32_t off = (uint32_t)(((k0 + lmod8 + 8 * l8) * 264 +
                                           wn * 64 + np * 16 + 8 * l16) * 2);
                ldsm4t(bh2, bb + off);
#pragma unroll
                for (int mt = 0; mt < 2; mt++) {
                    mma_f16(acc[mt][2*np],   ah[mt], bh2);
                    mma_f16(acc[mt][2*np+1], ah[mt], bh2 + 2);
                }
            }
        }
        if (sl < 3) { storeSlab((sl + 1) & 1); __syncthreads(); }
    }
    float* Sp = g_S + (size_t)(bh * NCH + ch) * (NN * NN);
#pragma unroll
    for (int mt = 0; mt < 2; mt++)
#pragma unroll
        for (int nt = 0; nt < 8; nt++)
#pragma unroll
            for (int h = 0; h < 2; h++) {
                int rr = m0g + wm * 32 + mt * 16 + lq + 8 * h;
                int cc = wn * 64 + nt * 8 + lr2;
                float2 o; o.x = acc[mt][nt][2*h]; o.y = acc[mt][nt][2*h+1];
                *(float2*)(Sp + (size_t)rr * NN + cc) = o;
            }
}

// ---------------- kernel 3: exclusive prefix scan + fp16 cvt (MLP) --------------
__global__ void k_scan() {
    int g = blockIdx.x * blockDim.x + threadIdx.x;
    if (g >= BH * NN * NN / 4) return;
    int bh = g >> 14;
    int e4 = (g & 16383) << 2;
    size_t base = (size_t)bh * NCH * (NN * NN) + e4;
    float4 vals[NCH - 1];
#pragma unroll
    for (int i = 0; i < NCH - 1; i++)
        vals[i] = *(const float4*)(g_S + base + (size_t)i * (NN * NN));
    float r0 = 0.f, r1 = 0.f, r2 = 0.f, r3 = 0.f;
#pragma unroll
    for (int i = 0; i < NCH; i++) {
        size_t p = base + (size_t)i * (NN * NN);
        uint2 H;
        H.x = cvtH2(r0, r1);
        H.y = cvtH2(r2, r3);
        *(uint2*)(g_Sh + p) = H;
        if (i < NCH - 1) { r0 += vals[i].x; r1 += vals[i].y; r2 += vals[i].z; r3 += vals[i].w; }
    }
}

// ---------------- kernel 4: Out = QR@S_pref + strict_tril(QR@KR^T)@V ------------
#define AT_BUF_A 10240
#define AT_B0    20480
#define AT_BUF_B 16896
#define AT_PH    54272
#define SMEM_ATTN 89088

// stage-1 warp->tile LUT (10 live lower-triangle tiles, 3/3/2/2 per SMSP)
#define S1_R_PACK 981476u
#define S1_C_PACK 54436u

__global__ void __launch_bounds__(512, 1) k_attn(const float* __restrict__ Q,
                                                 const float* __restrict__ K,
                                                 const float* __restrict__ V,
                                                 float* __restrict__ out) {
    extern __shared__ char sm[];
    uint32_t sb = smem_u32(sm);
    int tid = threadIdx.x, lane = tid & 31, wid = tid >> 5;
    int wm = wid >> 2, wn = wid & 3;
    int bh = blockIdx.x >> 4, ch = 15 - (blockIdx.x & 15);
    int t0 = ch * CC;
    int lm16 = lane & 15, l16 = lane >> 4, lmod8 = lane & 7, l8 = (lane >> 3) & 1;
    int lq = lane >> 2, lr2 = (lane & 3) * 2;

    const float* Qp = Q + (size_t)(bh * TT + t0) * NN;
    const float* Kp = K + (size_t)(bh * TT + t0) * NN;
    const float* Vp = V + (size_t)(bh * TT + t0) * NN;
    const __half* Sh = g_Sh + (size_t)(bh * NCH + ch) * (NN * NN);

    int sr = tid >> 2, sc8 = tid & 3;
    uint32_t s_so = (uint32_t)(sr * 80 + sc8 * 16);
    int vr = tid >> 5, vc8 = tid & 31;
    uint32_t v_so = (uint32_t)(vr * 528 + vc8 * 16);

    // ---- staging lambdas -----------------------------------------------------
    uint4 qh4, kh4;
    auto loadQK = [&](int sl) {
        int f = sl * 32 + sc8 * 8;
        float4 c = *(const float4*)(g_tabc + (t0 + sr) * 128 + (f >> 1));
        float4 s = *(const float4*)(g_tabs + (t0 + sr) * 128 + (f >> 1));
        qh4 = rope_cvt8_cs(Qp + (size_t)sr * NN + f, c, s);
        kh4 = rope_cvt8_cs(Kp + (size_t)sr * NN + f, c, s);
    };
    auto storeQK = [&](int buf) {
        char* ab = sm + buf * AT_BUF_A;
        *(uint4*)(ab + s_so) = qh4;
        char* bb = sm + AT_B0 + buf * AT_BUF_B;
        *(uint4*)(bb + s_so) = kh4;
    };
    auto loadQ2 = [&](int sl) {
        int f = sl * 32 + sc8 * 8;
        float4 c = *(const float4*)(g_tabc + (t0 + sr) * 128 + (f >> 1));
        float4 s = *(const float4*)(g_tabs + (t0 + sr) * 128 + (f >> 1));
        qh4 = rope_cvt8_cs(Qp + (size_t)sr * NN + f, c, s);
    };
    auto storeQ2 = [&](int buf) {
        char* ab = sm + buf * AT_BUF_A;
        *(uint4*)(ab + s_so) = qh4;
    };
    auto cpS = [&](int buf, int sl) {
        uint32_t bb = sb + AT_B0 + buf * AT_BUF_B;
        int f0 = sl * 32;
#pragma unroll
        for (int v = tid; v < 1024; v += 512) {
            int r = v >> 5, c8 = v & 31;
            uint32_t so = (uint32_t)(r * 528 + c8 * 16);
            cpa16(bb + so, Sh + (size_t)(f0 + r) * NN + c8 * 8);
        }
    };
    uint4 vh0, vh1;
    auto loadV3 = [&](int sl) {
        vh0 = cvt8(Vp + (size_t)(sl * 32 + vr) * NN + vc8 * 8);
        vh1 = cvt8(Vp + (size_t)(sl * 32 + vr + 16) * NN + vc8 * 8);
    };
    auto storeV3 = [&](int buf) {
        char* bb = sm + AT_B0 + buf * AT_BUF_B;
        *(uint4*)(bb + v_so) = vh0;
        *(uint4*)(bb + 8448 + v_so) = vh1;
    };

    int pr = (S1_R_PACK >> (wid * 2)) & 3;
    int pc = (S1_C_PACK >> (wid * 2)) & 3;
    bool act1 = (wid < 10);

    // ======== Stage 1: P = QR @ KR^T, lower-triangle tiles only ================
    float acc1[2][4][4];
#pragma unroll
    for (int a = 0; a < 2; a++)
#pragma unroll
        for (int b = 0; b < 4; b++)
#pragma unroll
            for (int c = 0; c < 4; c++) acc1[a][b][c] = 0.f;

    loadQK(0);
    storeQK(0);
    __syncthreads();
    for (int sl = 0; sl < 8; sl++) {
        if (sl < 7) loadQK(sl + 1);
        else if (ch > 0) { cpS(0, 6); CP_COMMIT(); }   // S slab 6 -> buf0 (K buf0 dead)
        if (act1) {
            uint32_t ab = sb + (sl & 1) * AT_BUF_A;
            uint32_t bb = sb + AT_B0 + (sl & 1) * AT_BUF_B;
#pragma unroll
            for (int k0 = 0; k0 < 32; k0 += 16) {
                uint32_t ah[2][4];
#pragma unroll
                for (int mt = 0; mt < 2; mt++) {
                    uint32_t off = (uint32_t)(((pr * 32 + mt * 16 + lm16) * 40 +
                                               k0 + 8 * l16) * 2);
                    ldsm4(ah[mt], ab + off);
                }
#pragma unroll
                for (int np = 0; np < 2; np++) {
                    uint32_t bh2[4];
                    uint32_t off = (uint32_t)(((pc * 32 + np * 16 + lmod8 + 8 * l16) * 40 +
                                               k0 + 8 * l8) * 2);
                    ldsm4(bh2, bb + off);
#pragma unroll
                    for (int mt = 0; mt < 2; mt++) {
                        mma_f16(acc1[mt][2*np],   ah[mt], bh2);
                        mma_f16(acc1[mt][2*np+1], ah[mt], bh2 + 2);
                    }
                }
            }
        }
        if (sl < 7) { storeQK((sl + 1) & 1); __syncthreads(); }
    }
    __syncthreads();                       // all sl=7 MMAs done (K buf1 free)
    if (ch > 0) { cpS(1, 7); CP_COMMIT(); }   // S slab 7 -> buf1, overlaps P writes
    else loadV3(0);                           // ch=0: prefetch stage-3 V

    // mask (strict lower triangle) + fp16 cvt into smem P (live tiles only)
    if (act1) {
#pragma unroll
        for (int mt = 0; mt < 2; mt++)
#pragma unroll
            for (int nt = 0; nt < 4; nt++)
#pragma unroll
                for (int h = 0; h < 2; h++) {
                    int rr = pr * 32 + mt * 16 + lq + 8 * h;
                    int cn = pc * 32 + nt * 8 + lr2;
                    float v0 = (cn     < rr) ? acc1[mt][nt][2*h]   : 0.f;
                    float v1 = (cn + 1 < rr) ? acc1[mt][nt][2*h+1] : 0.f;
                    uint32_t hbits = cvtH2(v0, v1);
                    uint32_t bo = (uint32_t)((rr * 136 + cn) * 2);
                    *(uint32_t*)(sm + AT_PH + bo) = hbits;
                }
    }
    if (ch > 0) CP_WAIT0();
    __syncthreads();

    // ======== Stage 2: D = QR @ S_pref, slab order {6,7,0..5} ==================
    float acc[2][8][4];
#pragma unroll
    for (int a = 0; a < 2; a++)
#pragma unroll
        for (int b = 0; b < 8; b++)
#pragma unroll
            for (int c = 0; c < 4; c++) acc[a][b][c] = 0.f;

    if (ch > 0) {
        for (int i = 0; i < 8; i++) {
            if (i >= 1 && i < 7) {
                int sn = (7 + i) & 7;               // next slab
                loadQ2(sn);
                cpS((i + 1) & 1, sn);
                CP_COMMIT();
            } else if (i == 7) loadV3(0);           // prefetch stage-3 V slab 0
            uint32_t ab = sb + (i & 1) * AT_BUF_A;
            uint32_t bb = sb + AT_B0 + (i & 1) * AT_BUF_B;
#pragma unroll
            for (int k0 = 0; k0 < 32; k0 += 16) {
                uint32_t ah[2][4];
#pragma unroll
                for (int mt = 0; mt < 2; mt++) {
                    uint32_t off = (uint32_t)(((wm * 32 + mt * 16 + lm16) * 40 +
                                               k0 + 8 * l16) * 2);
                    ldsm4(ah[mt], ab + off);
                }
#pragma unroll
                for (int np = 0; np < 4; np++) {
                    uint32_t bh2[4];
                    uint32_t off = (uint32_t)(((k0 + lmod8 + 8 * l8) * 264 +
                                               wn * 64 + np * 16 + 8 * l16) * 2);
                    ldsm4t(bh2, bb + off);
#pragma unroll
                    for (int mt = 0; mt < 2; mt++) {
                        mma_f16(acc[mt][2*np],   ah[mt], bh2);
                        mma_f16(acc[mt][2*np+1], ah[mt], bh2 + 2);
                    }
                }
            }
            if (i < 7) {
                if (i >= 1) storeQ2((i + 1) & 1);
                CP_WAIT0();
                __syncthreads();
            }
        }
    }

    // ======== Stage 3: D += P @ V — skip slabs above warp's diagonal ===========
    storeV3(0);                            // buf0 free (last read at i=6 / ch=0: stage1 sl=6)
    __syncthreads();
    for (int sl = 0; sl < 4; sl++) {
        if (sl < 3) loadV3(sl + 1);
        if (sl <= wm) {
            int s0 = sl * 32;
            uint32_t bb = sb + AT_B0 + (sl & 1) * AT_BUF_B;
#pragma unroll
            for (int k0 = 0; k0 < 32; k0 += 16) {
                uint32_t ah[2][4];
#pragma unroll
                for (int mt = 0; mt < 2; mt++) {
                    uint32_t off = (uint32_t)(((wm * 32 + mt * 16 + lm16) * 136 +
                                               s0 + k0 + 8 * l16) * 2);
                    ldsm4(ah[mt], sb + AT_PH + off);
                }
#pragma unroll
                for (int np = 0; np < 4; np++) {
                    uint32_t bh2[4];
                    uint32_t off = (uint32_t)(((k0 + lmod8 + 8 * l8) * 264 +
                                               wn * 64 + np * 16 + 8 * l16) * 2);
                    ldsm4t(bh2, bb + off);
#pragma unroll
                    for (int mt = 0; mt < 2; mt++) {
                        mma_f16(acc[mt][2*np],   ah[mt], bh2);
                        mma_f16(acc[mt][2*np+1], ah[mt], bh2 + 2);
                    }
                }
            }
        }
        if (sl < 3) { storeV3((sl + 1) & 1); __syncthreads(); }
    }

    // epilogue
#pragma unroll
    for (int mt = 0; mt < 2; mt++)
#pragma unroll
        for (int nt = 0; nt < 8; nt++)
#pragma unroll
            for (int h = 0; h < 2; h++) {
                int rr = wm * 32 + mt * 16 + lq + 8 * h;
                int cc = wn * 64 + nt * 8 + lr2;
                float2 o; o.x = acc[mt][nt][2*h]; o.y = acc[mt][nt][2*h+1];
                *(float2*)(out + (size_t)(bh * TT + t0 + rr) * NN + cc) = o;
            }
}

// ---------------- launcher -------------------------------------------------------
extern "C" void kernel_launch(void* const* d_in, const int* in_sizes, int n_in,
                              void* d_out, int out_size) {
    const float* Q = (const float*)d_in[0];
    const float* K = (const float*)d_in[1];
    const float* V = (const float*)d_in[2];
    float* out = (float*)d_out;

    static bool attr_set = false;
    if (!attr_set) {
        cudaFuncSetAttribute(k_kv,   cudaFuncAttributeMaxDynamicSharedMemorySize, SMEM_KV);
        cudaFuncSetAttribute(k_attn, cudaFuncAttributeMaxDynamicSharedMemorySize, SMEM_ATTN);
        attr_set = true;
    }

    k_tables<<<512, 512>>>();
    k_kv<<<dim3(BH * (NCH - 1), 2), 512, SMEM_KV>>>(K, V);
    k_scan<<<(BH * NN * NN / 4 + 255) / 256, 256>>>();
    k_attn<<<BH * NCH, 512, SMEM_ATTN>>>(Q, K, V, out);
}

// round 14
// speedup vs baseline: 1.5935x; 1.0632x over previous
#include <cuda_runtime.h>
#include <cuda_fp16.h>
#include <math.h>
#include <stdint.h>

#define BH   24
#define TT   2048
#define NN   256
#define CC   128
#define NCH  16

// ---------------- device scratch ----------------------------------------------
__device__ float g_tabc[TT * (NN/2)];
__device__ float g_tabs[TT * (NN/2)];
__device__ float g_S[BH*NCH*NN*NN];
__device__ __half g_Sh[BH*NCH*NN*NN];

// ---------------- PTX helpers ---------------------------------------------------
__device__ __forceinline__ uint32_t smem_u32(const void* p) {
    uint32_t a;
    asm("{ .reg .u64 t; cvta.to.shared.u64 t, %1; cvt.u32.u64 %0, t; }" : "=r"(a) : "l"(p));
    return a;
}
__device__ __forceinline__ void cpa16(uint32_t s, const void* g) {
    asm volatile("cp.async.cg.shared.global [%0], [%1], 16;" :: "r"(s), "l"(g));
}
#define CP_COMMIT() asm volatile("cp.async.commit_group;" ::: "memory")
#define CP_WAIT0()  asm volatile("cp.async.wait_group 0;" ::: "memory")
#define CP_WAIT1()  asm volatile("cp.async.wait_group 1;" ::: "memory")

__device__ __forceinline__ void ldsm4(uint32_t* r, uint32_t a) {
    asm volatile("ldmatrix.sync.aligned.m8n8.x4.shared.b16 {%0,%1,%2,%3}, [%4];"
        : "=r"(r[0]), "=r"(r[1]), "=r"(r[2]), "=r"(r[3]) : "r"(a));
}
__device__ __forceinline__ void ldsm4t(uint32_t* r, uint32_t a) {
    asm volatile("ldmatrix.sync.aligned.m8n8.x4.trans.shared.b16 {%0,%1,%2,%3}, [%4];"
        : "=r"(r[0]), "=r"(r[1]), "=r"(r[2]), "=r"(r[3]) : "r"(a));
}
__device__ __forceinline__ void mma_f16(float* d, const uint32_t* a, const uint32_t* b) {
    asm volatile("mma.sync.aligned.m16n8k16.row.col.f32.f16.f16.f32 "
        "{%0,%1,%2,%3}, {%4,%5,%6,%7}, {%8,%9}, {%0,%1,%2,%3};"
        : "+f"(d[0]), "+f"(d[1]), "+f"(d[2]), "+f"(d[3])
        : "r"(a[0]), "r"(a[1]), "r"(a[2]), "r"(a[3]), "r"(b[0]), "r"(b[1]));
}

// ---------------- fp16 cvt helpers -----------------------------------------------
__device__ __forceinline__ uint32_t cvtH2(float x, float y) {
    __half2 H = __floats2half2_rn(x, y);
    return *(uint32_t*)&H;
}
__device__ __forceinline__ uint4 rope_cvt8_cs(const float* __restrict__ src,
                                              float4 c, float4 s) {
    float4 a = *(const float4*)(src);
    float4 b = *(const float4*)(src + 4);
    uint4 h;
    h.x = cvtH2(a.x*c.x - a.y*s.x, a.y*c.x + a.x*s.x);
    h.y = cvtH2(a.z*c.y - a.w*s.y, a.w*c.y + a.z*s.y);
    h.z = cvtH2(b.x*c.z - b.y*s.z, b.y*c.z + b.x*s.z);
    h.w = cvtH2(b.z*c.w - b.w*s.w, b.w*c.w + b.z*s.w);
    return h;
}
__device__ __forceinline__ uint4 rope_cvt8(const float* __restrict__ src, int t, int f) {
    float4 c = *(const float4*)(g_tabc + t * 128 + (f >> 1));
    float4 s = *(const float4*)(g_tabs + t * 128 + (f >> 1));
    return rope_cvt8_cs(src, c, s);
}
__device__ __forceinline__ uint4 cvt8(const float* __restrict__ src) {
    float4 a = *(const float4*)(src);
    float4 b = *(const float4*)(src + 4);
    uint4 h;
    h.x = cvtH2(a.x, a.y); h.y = cvtH2(a.z, a.w);
    h.z = cvtH2(b.x, b.y); h.w = cvtH2(b.z, b.w);
    return h;
}

// ---------------- kernel 1: RoPE phase tables -----------------------------------
__global__ void k_tables() {
    int id = blockIdx.x * blockDim.x + threadIdx.x;
    if (id >= TT * (NN/2)) return;
    int t = id >> 7;
    int j = id & 127;
    double fr_d = exp2(-(double)j / 8.0) / (2.0 * 3.14159265358979323846);
    float f32 = (float)fr_d;
    float ph  = (float)t * f32;
    ph = ph - floorf(ph);
    float ang = ph * 6.28318530717958647692f;
    double angd = (double)ang;
    g_tabc[id] = (float)cos(angd);
    g_tabs[id] = (float)sin(angd);
}

// ---------------- kernel 2: chunk KV state S_ch = KR^T @ V (64-t slabs) ---------
#define KV_BUF_A 17408
#define KV_B0    34816
#define KV_BUF_B 33792
#define SMEM_KV  102400

__global__ void __launch_bounds__(512, 1) k_kv(const float* __restrict__ K,
                                               const float* __restrict__ V) {
    extern __shared__ char sm[];
    uint32_t sb = smem_u32(sm);
    int tid = threadIdx.x, lane = tid & 31, wid = tid >> 5;
    int wm = wid >> 2, wn = wid & 3;
    int bx = blockIdx.x;
    int bh = bx / 15, ch = bx % 15;
    int m0g = blockIdx.y * 128;
    int t0 = ch * CC;
    int l16 = lane >> 4, lmod8 = lane & 7, l8 = (lane >> 3) & 1;
    int lq = lane >> 2, lr2 = (lane & 3) * 2;

    const float* Kp = K + (size_t)(bh * TT + t0) * NN;
    const float* Vp = V + (size_t)(bh * TT + t0) * NN;

    int ar = tid >> 4, ac8 = tid & 15;          // A rows ar, ar+32 (of 64)
    uint32_t a_so = (uint32_t)(ar * 272 + ac8 * 16);
    int vr = tid >> 5, vc8 = tid & 31;          // V rows vr,+16,+32,+48
    uint32_t v_so = (uint32_t)(vr * 528 + vc8 * 16);

    uint4 ah4a, ah4b, vh[4];
    auto loadSlab = [&](int sl) {
        int r0 = sl * 64;
        ah4a = rope_cvt8(Kp + (size_t)(r0 + ar) * NN + m0g + ac8 * 8,
                         t0 + r0 + ar, m0g + ac8 * 8);
        ah4b = rope_cvt8(Kp + (size_t)(r0 + ar + 32) * NN + m0g + ac8 * 8,
                         t0 + r0 + ar + 32, m0g + ac8 * 8);
#pragma unroll
        for (int j = 0; j < 4; j++)
            vh[j] = cvt8(Vp + (size_t)(r0 + vr + 16 * j) * NN + vc8 * 8);
    };
    auto storeSlab = [&](int buf) {
        char* ab = sm + buf * KV_BUF_A;
        *(uint4*)(ab + a_so) = ah4a;
        *(uint4*)(ab + 8704 + a_so) = ah4b;     // row+32: 32*272 = 8704
        char* bb = sm + KV_B0 + buf * KV_BUF_B;
#pragma unroll
        for (int j = 0; j < 4; j++)
            *(uint4*)(bb + j * 8448 + v_so) = vh[j];   // 16 rows * 528
    };

    float acc[2][8][4];
#pragma unroll
    for (int a = 0; a < 2; a++)
#pragma unroll
        for (int b = 0; b < 8; b++)
#pragma unroll
            for (int c = 0; c < 4; c++) acc[a][b][c] = 0.f;

    loadSlab(0);
    storeSlab(0);
    __syncthreads();
    for (int sl = 0; sl < 2; sl++) {
        if (sl == 0) loadSlab(1);
        uint32_t ab = sb + sl * KV_BUF_A;
        uint32_t bb = sb + KV_B0 + sl * KV_BUF_B;
#pragma unroll
        for (int k0 = 0; k0 < 64; k0 += 16) {
            uint32_t ah[2][4];
#pragma unroll
            for (int mt = 0; mt < 2; mt++) {
                uint32_t off = (uint32_t)(((k0 + lmod8 + 8 * l16) * 136 +
                                           wm * 32 + mt * 16 + 8 * l8) * 2);
                ldsm4t(ah[mt], ab + off);
            }
#pragma unroll
            for (int np = 0; np < 4; np++) {
                uint32_t bh2[4];
                uint32_t off = (uint32_t)(((k0 + lmod8 + 8 * l8) * 264 +
                                           wn * 64 + np * 16 + 8 * l16) * 2);
                ldsm4t(bh2, bb + off);
#pragma unroll
                for (int mt = 0; mt < 2; mt++) {
                    mma_f16(acc[mt][2*np],   ah[mt], bh2);
                    mma_f16(acc[mt][2*np+1], ah[mt], bh2 + 2);
                }
            }
        }
        if (sl == 0) { storeSlab(1); __syncthreads(); }
    }
    float* Sp = g_S + (size_t)(bh * NCH + ch) * (NN * NN);
#pragma unroll
    for (int mt = 0; mt < 2; mt++)
#pragma unroll
        for (int nt = 0; nt < 8; nt++)
#pragma unroll
            for (int h = 0; h < 2; h++) {
                int rr = m0g + wm * 32 + mt * 16 + lq + 8 * h;
                int cc = wn * 64 + nt * 8 + lr2;
                float2 o; o.x = acc[mt][nt][2*h]; o.y = acc[mt][nt][2*h+1];
                *(float2*)(Sp + (size_t)rr * NN + cc) = o;
            }
}

// ---------------- kernel 3: exclusive prefix scan + fp16 cvt (MLP) --------------
__global__ void k_scan() {
    int g = blockIdx.x * blockDim.x + threadIdx.x;
    if (g >= BH * NN * NN / 4) return;
    int bh = g >> 14;
    int e4 = (g & 16383) << 2;
    size_t base = (size_t)bh * NCH * (NN * NN) + e4;
    float4 vals[NCH - 1];
#pragma unroll
    for (int i = 0; i < NCH - 1; i++)
        vals[i] = *(const float4*)(g_S + base + (size_t)i * (NN * NN));
    float r0 = 0.f, r1 = 0.f, r2 = 0.f, r3 = 0.f;
#pragma unroll
    for (int i = 0; i < NCH; i++) {
        size_t p = base + (size_t)i * (NN * NN);
        uint2 H;
        H.x = cvtH2(r0, r1);
        H.y = cvtH2(r2, r3);
        *(uint2*)(g_Sh + p) = H;
        if (i < NCH - 1) { r0 += vals[i].x; r1 += vals[i].y; r2 += vals[i].z; r3 += vals[i].w; }
    }
}

// ---------------- kernel 4: Out = QR@S_pref + strict_tril(QR@KR^T)@V ------------
// Q persistent in smem across stages 1-2: 4 slabs [128][72] halves.
#define AT_QBUF  18432
#define AT_B0    73728
#define AT_BUF_B 33792
#define AT_PH    141312
#define SMEM_ATTN 176128

// stage-1 warp->tile LUT (10 live lower-triangle tiles, 3/3/2/2 per SMSP)
#define S1_R_PACK 981476u
#define S1_C_PACK 54436u

__global__ void __launch_bounds__(512, 1) k_attn(const float* __restrict__ Q,
                                                 const float* __restrict__ K,
                                                 const float* __restrict__ V,
                                                 float* __restrict__ out) {
    extern __shared__ char sm[];
    uint32_t sb = smem_u32(sm);
    int tid = threadIdx.x, lane = tid & 31, wid = tid >> 5;
    int wm = wid >> 2, wn = wid & 3;
    int bh = blockIdx.x >> 4, ch = 15 - (blockIdx.x & 15);
    int t0 = ch * CC;
    int lm16 = lane & 15, l16 = lane >> 4, lmod8 = lane & 7, l8 = (lane >> 3) & 1;
    int lq = lane >> 2, lr2 = (lane & 3) * 2;

    const float* Qp = Q + (size_t)(bh * TT + t0) * NN;
    const float* Kp = K + (size_t)(bh * TT + t0) * NN;
    const float* Vp = V + (size_t)(bh * TT + t0) * NN;
    const __half* Sh = g_Sh + (size_t)(bh * NCH + ch) * (NN * NN);

    int sr = tid >> 2, sc8 = tid & 3;           // row 0..127, feature group 0..3
    uint32_t s_so1 = (uint32_t)((sr * 72 + sc8 * 8) * 2);
    uint32_t s_so2 = (uint32_t)((sr * 72 + 32 + sc8 * 8) * 2);
    int vr = tid >> 5, vc8 = tid & 31;
    uint32_t v_so = (uint32_t)(vr * 528 + vc8 * 16);

    // ---- staging lambdas -----------------------------------------------------
    uint4 qa, qb, ka, kb;
    auto loadQK = [&](int sl) {
        int f1 = sl * 64 + sc8 * 8;
        float4 c1 = *(const float4*)(g_tabc + (t0 + sr) * 128 + (f1 >> 1));
        float4 s1 = *(const float4*)(g_tabs + (t0 + sr) * 128 + (f1 >> 1));
        float4 c2 = *(const float4*)(g_tabc + (t0 + sr) * 128 + (f1 >> 1) + 16);
        float4 s2 = *(const float4*)(g_tabs + (t0 + sr) * 128 + (f1 >> 1) + 16);
        qa = rope_cvt8_cs(Qp + (size_t)sr * NN + f1, c1, s1);
        qb = rope_cvt8_cs(Qp + (size_t)sr * NN + f1 + 32, c2, s2);
        ka = rope_cvt8_cs(Kp + (size_t)sr * NN + f1, c1, s1);
        kb = rope_cvt8_cs(Kp + (size_t)sr * NN + f1 + 32, c2, s2);
    };
    auto storeQK = [&](int sl) {
        char* qbuf = sm + sl * AT_QBUF;          // persistent, indexed by slab
        *(uint4*)(qbuf + s_so1) = qa;
        *(uint4*)(qbuf + s_so2) = qb;
        char* kbuf = sm + AT_B0 + (sl & 1) * AT_BUF_B;
        *(uint4*)(kbuf + s_so1) = ka;
        *(uint4*)(kbuf + s_so2) = kb;
    };
    auto cpS = [&](int buf, int sl) {            // S slab: rows [sl*64, sl*64+64)
        uint32_t bb = sb + AT_B0 + buf * AT_BUF_B;
        int f0 = sl * 64;
#pragma unroll
        for (int v = tid; v < 2048; v += 512) {
            int r = v >> 5, c8 = v & 31;
            uint32_t so = (uint32_t)(r * 528 + c8 * 16);
            cpa16(bb + so, Sh + (size_t)(f0 + r) * NN + c8 * 8);
        }
    };
    uint4 vh0, vh1;
    auto loadV3 = [&](int sl) {
        vh0 = cvt8(Vp + (size_t)(sl * 32 + vr) * NN + vc8 * 8);
        vh1 = cvt8(Vp + (size_t)(sl * 32 + vr + 16) * NN + vc8 * 8);
    };
    auto storeV3 = [&](int buf) {
        char* bb = sm + AT_B0 + buf * AT_BUF_B;
        *(uint4*)(bb + v_so) = vh0;
        *(uint4*)(bb + 8448 + v_so) = vh1;
    };

    int pr = (S1_R_PACK >> (wid * 2)) & 3;
    int pc = (S1_C_PACK >> (wid * 2)) & 3;
    bool act1 = (wid < 10);

    // ======== Stage 1: P = QR @ KR^T, lower-triangle tiles only ================
    float acc1[2][4][4];
#pragma unroll
    for (int a = 0; a < 2; a++)
#pragma unroll
        for (int b = 0; b < 4; b++)
#pragma unroll
            for (int c = 0; c < 4; c++) acc1[a][b][c] = 0.f;

    loadQK(0);
    storeQK(0);
    __syncthreads();
    for (int sl = 0; sl < 4; sl++) {
        if (sl < 3) loadQK(sl + 1);
        else if (ch > 0) { cpS(0, 0); CP_COMMIT(); }   // S slab0 -> Kbuf0 (dead)
        if (act1) {
            uint32_t ab = sb + sl * AT_QBUF;
            uint32_t bb = sb + AT_B0 + (sl & 1) * AT_BUF_B;
#pragma unroll
            for (int k0 = 0; k0 < 64; k0 += 16) {
                uint32_t ah[2][4];
#pragma unroll
                for (int mt = 0; mt < 2; mt++) {
                    uint32_t off = (uint32_t)(((pr * 32 + mt * 16 + lm16) * 72 +
                                               k0 + 8 * l16) * 2);
                    ldsm4(ah[mt], ab + off);
                }
#pragma unroll
                for (int np = 0; np < 2; np++) {
                    uint32_t bh2[4];
                    uint32_t off = (uint32_t)(((pc * 32 + np * 16 + lmod8 + 8 * l16) * 72 +
                                               k0 + 8 * l8) * 2);
                    ldsm4(bh2, bb + off);
#pragma unroll
                    for (int mt = 0; mt < 2; mt++) {
                        mma_f16(acc1[mt][2*np],   ah[mt], bh2);
                        mma_f16(acc1[mt][2*np+1], ah[mt], bh2 + 2);
                    }
                }
            }
        }
        if (sl < 3) { storeQK(sl + 1); __syncthreads(); }
    }
    __syncthreads();                       // all sl=3 MMAs done (Kbuf1 free)
    if (ch > 0) { cpS(1, 1); CP_COMMIT(); }   // S slab1 -> buf1, overlaps P writes
    else loadV3(0);                           // ch=0: prefetch stage-3 V

    // mask (strict lower triangle) + fp16 cvt into smem P (live tiles only)
    if (act1) {
#pragma unroll
        for (int mt = 0; mt < 2; mt++)
#pragma unroll
            for (int nt = 0; nt < 4; nt++)
#pragma unroll
                for (int h = 0; h < 2; h++) {
                    int rr = pr * 32 + mt * 16 + lq + 8 * h;
                    int cn = pc * 32 + nt * 8 + lr2;
                    float v0 = (cn     < rr) ? acc1[mt][nt][2*h]   : 0.f;
                    float v1 = (cn + 1 < rr) ? acc1[mt][nt][2*h+1] : 0.f;
                    uint32_t hbits = cvtH2(v0, v1);
                    uint32_t bo = (uint32_t)((rr * 136 + cn) * 2);
                    *(uint32_t*)(sm + AT_PH + bo) = hbits;
                }
    }
    if (ch > 0) CP_WAIT1();                // S slab0 complete (slab1 may be in flight)
    __syncthreads();

    // ======== Stage 2: D = QR @ S_pref (Q from persistent smem) ================
    float acc[2][8][4];
#pragma unroll
    for (int a = 0; a < 2; a++)
#pragma unroll
        for (int b = 0; b < 8; b++)
#pragma unroll
            for (int c = 0; c < 4; c++) acc[a][b][c] = 0.f;

    if (ch > 0) {
        for (int i = 0; i < 4; i++) {
            if (i >= 1 && i < 3) { cpS((i + 1) & 1, i + 1); CP_COMMIT(); }
            else if (i == 3) loadV3(0);        // prefetch stage-3 V slab 0
            uint32_t ab = sb + i * AT_QBUF;
            uint32_t bb = sb + AT_B0 + (i & 1) * AT_BUF_B;
#pragma unroll
            for (int k0 = 0; k0 < 64; k0 += 16) {
                uint32_t ah[2][4];
#pragma unroll
                for (int mt = 0; mt < 2; mt++) {
                    uint32_t off = (uint32_t)(((wm * 32 + mt * 16 + lm16) * 72 +
                                               k0 + 8 * l16) * 2);
                    ldsm4(ah[mt], ab + off);
                }
#pragma unroll
                for (int np = 0; np < 4; np++) {
                    uint32_t bh2[4];
                    uint32_t off = (uint32_t)(((k0 + lmod8 + 8 * l8) * 264 +
                                               wn * 64 + np * 16 + 8 * l16) * 2);
                    ldsm4t(bh2, bb + off);
#pragma unroll
                    for (int mt = 0; mt < 2; mt++) {
                        mma_f16(acc[mt][2*np],   ah[mt], bh2);
                        mma_f16(acc[mt][2*np+1], ah[mt], bh2 + 2);
                    }
                }
            }
            if (i < 3) { CP_WAIT0(); __syncthreads(); }
        }
        __syncthreads();                   // i=3 MMAs done before V reuses buf
    }

    // ======== Stage 3: D += P @ V — skip slabs above warp's diagonal ===========
    storeV3(0);
    __syncthreads();
    for (int sl = 0; sl < 4; sl++) {
        if (sl < 3) loadV3(sl + 1);
        if (sl <= wm) {
            int s0 = sl * 32;
            uint32_t bb = sb + AT_B0 + (sl & 1) * AT_BUF_B;
#pragma unroll
            for (int k0 = 0; k0 < 32; k0 += 16) {
                uint32_t ah[2][4];
#pragma unroll
                for (int mt = 0; mt < 2; mt++) {
                    uint32_t off = (uint32_t)(((wm * 32 + mt * 16 + lm16) * 136 +
                                               s0 + k0 + 8 * l16) * 2);
                    ldsm4(ah[mt], sb + AT_PH + off);
                }
#pragma unroll
                for (int np = 0; np < 4; np++) {
                    uint32_t bh2[4];
                    uint32_t off = (uint32_t)(((k0 + lmod8 + 8 * l8) * 264 +
                                               wn * 64 + np * 16 + 8 * l16) * 2);
                    ldsm4t(bh2, bb + off);
#pragma unroll
                    for (int mt = 0; mt < 2; mt++) {
                        mma_f16(acc[mt][2*np],   ah[mt], bh2);
                        mma_f16(acc[mt][2*np+1], ah[mt], bh2 + 2);
                    }
                }
            }
        }
        if (sl < 3) { storeV3((sl + 1) & 1); __syncthreads(); }
    }

    // epilogue
#pragma unroll
    for (int mt = 0; mt < 2; mt++)
#pragma unroll
        for (int nt = 0; nt < 8; nt++)
#pragma unroll
            for (int h = 0; h < 2; h++) {
                int rr = wm * 32 + mt * 16 + lq + 8 * h;
                int cc = wn * 64 + nt * 8 + lr2;
                float2 o; o.x = acc[mt][nt][2*h]; o.y = acc[mt][nt][2*h+1];
                *(float2*)(out + (size_t)(bh * TT + t0 + rr) * NN + cc) = o;
            }
}

// ---------------- launcher -------------------------------------------------------
extern "C" void kernel_launch(void* const* d_in, const int* in_sizes, int n_in,
                              void* d_out, int out_size) {
    const float* Q = (const float*)d_in[0];
    const float* K = (const float*)d_in[1];
    const float* V = (const float*)d_in[2];
    float* out = (float*)d_out;

    static bool attr_set = false;
    if (!attr_set) {
        cudaFuncSetAttribute(k_kv,   cudaFuncAttributeMaxDynamicSharedMemorySize, SMEM_KV);
        cudaFuncSetAttribute(k_attn, cudaFuncAttributeMaxDynamicSharedMemorySize, SMEM_ATTN);
        attr_set = true;
    }

    k_tables<<<512, 512>>>();
    k_kv<<<dim3(BH * (NCH - 1), 2), 512, SMEM_KV>>>(K, V);
    k_scan<<<(BH * NN * NN / 4 + 255) / 256, 256>>>();
    k_attn<<<BH * NCH, 512, SMEM_ATTN>>>(Q, K, V, out);
}

// round 15
// speedup vs baseline: 1.6626x; 1.0434x over previous
#include <cuda_runtime.h>
#include <cuda_fp16.h>
#include <math.h>
#include <stdint.h>

#define BH   24
#define TT   2048
#define NN   256
#define CC   128
#define NCH  16

// ---------------- device scratch ----------------------------------------------
__device__ float g_tabc[TT * (NN/2)];
__device__ float g_tabs[TT * (NN/2)];
__device__ __half g_S16[BH*NCH*NN*NN];        // per-chunk K^T V, fp16
__device__ __half g_Sh [BH*NCH*NN*NN];        // exclusive prefix, fp16

// ---------------- PTX helpers ---------------------------------------------------
__device__ __forceinline__ uint32_t smem_u32(const void* p) {
    uint32_t a;
    asm("{ .reg .u64 t; cvta.to.shared.u64 t, %1; cvt.u32.u64 %0, t; }" : "=r"(a) : "l"(p));
    return a;
}
__device__ __forceinline__ void cpa16(uint32_t s, const void* g) {
    asm volatile("cp.async.cg.shared.global [%0], [%1], 16;" :: "r"(s), "l"(g));
}
#define CP_COMMIT() asm volatile("cp.async.commit_group;" ::: "memory")
#define CP_WAIT0()  asm volatile("cp.async.wait_group 0;" ::: "memory")
#define CP_WAIT1()  asm volatile("cp.async.wait_group 1;" ::: "memory")

__device__ __forceinline__ void ldsm4(uint32_t* r, uint32_t a) {
    asm volatile("ldmatrix.sync.aligned.m8n8.x4.shared.b16 {%0,%1,%2,%3}, [%4];"
        : "=r"(r[0]), "=r"(r[1]), "=r"(r[2]), "=r"(r[3]) : "r"(a));
}
__device__ __forceinline__ void ldsm4t(uint32_t* r, uint32_t a) {
    asm volatile("ldmatrix.sync.aligned.m8n8.x4.trans.shared.b16 {%0,%1,%2,%3}, [%4];"
        : "=r"(r[0]), "=r"(r[1]), "=r"(r[2]), "=r"(r[3]) : "r"(a));
}
__device__ __forceinline__ void mma_f16(float* d, const uint32_t* a, const uint32_t* b) {
    asm volatile("mma.sync.aligned.m16n8k16.row.col.f32.f16.f16.f32 "
        "{%0,%1,%2,%3}, {%4,%5,%6,%7}, {%8,%9}, {%0,%1,%2,%3};"
        : "+f"(d[0]), "+f"(d[1]), "+f"(d[2]), "+f"(d[3])
        : "r"(a[0]), "r"(a[1]), "r"(a[2]), "r"(a[3]), "r"(b[0]), "r"(b[1]));
}

// ---------------- fp16 cvt helpers -----------------------------------------------
__device__ __forceinline__ uint32_t cvtH2(float x, float y) {
    __half2 H = __floats2half2_rn(x, y);
    return *(uint32_t*)&H;
}
__device__ __forceinline__ uint4 rope_cvt8_cs(const float* __restrict__ src,
                                              float4 c, float4 s) {
    float4 a = *(const float4*)(src);
    float4 b = *(const float4*)(src + 4);
    uint4 h;
    h.x = cvtH2(a.x*c.x - a.y*s.x, a.y*c.x + a.x*s.x);
    h.y = cvtH2(a.z*c.y - a.w*s.y, a.w*c.y + a.z*s.y);
    h.z = cvtH2(b.x*c.z - b.y*s.z, b.y*c.z + b.x*s.z);
    h.w = cvtH2(b.z*c.w - b.w*s.w, b.w*c.w + b.z*s.w);
    return h;
}
__device__ __forceinline__ uint4 rope_cvt8(const float* __restrict__ src, int t, int f) {
    float4 c = *(const float4*)(g_tabc + t * 128 + (f >> 1));
    float4 s = *(const float4*)(g_tabs + t * 128 + (f >> 1));
    return rope_cvt8_cs(src, c, s);
}
__device__ __forceinline__ uint4 cvt8(const float* __restrict__ src) {
    float4 a = *(const float4*)(src);
    float4 b = *(const float4*)(src + 4);
    uint4 h;
    h.x = cvtH2(a.x, a.y); h.y = cvtH2(a.z, a.w);
    h.z = cvtH2(b.x, b.y); h.w = cvtH2(b.z, b.w);
    return h;
}

// ---------------- kernel 1: RoPE phase tables -----------------------------------
__global__ void k_tables() {
    int id = blockIdx.x * blockDim.x + threadIdx.x;
    if (id >= TT * (NN/2)) return;
    int t = id >> 7;
    int j = id & 127;
    double fr_d = exp2(-(double)j / 8.0) / (2.0 * 3.14159265358979323846);
    float f32 = (float)fr_d;
    float ph  = (float)t * f32;
    ph = ph - floorf(ph);
    float ang = ph * 6.28318530717958647692f;
    double angd = (double)ang;
    g_tabc[id] = (float)cos(angd);
    g_tabs[id] = (float)sin(angd);
}

// ---------------- kernel 2: chunk KV state, V resident, both m-halves -----------
// S_ch[m][n] = sum_t rope(K)[t][m] * V[t][n];  one CTA per (bh, ch).
#define KVV_SM   0                       // V: 128 rows x 528 B = 67584
#define KVA_0    67584                   // K tiles: 2 x [64t][136m] fp16
#define KV_BUF_A 17408
#define SMEM_KV  102400

__global__ void __launch_bounds__(512, 1) k_kv(const float* __restrict__ K,
                                               const float* __restrict__ V) {
    extern __shared__ char sm[];
    uint32_t sb = smem_u32(sm);
    int tid = threadIdx.x, lane = tid & 31, wid = tid >> 5;
    int wm = wid >> 2, wn = wid & 3;
    int bx = blockIdx.x;
    int bh = bx / 15, ch = bx % 15;
    int t0 = ch * CC;
    int l16 = lane >> 4, lmod8 = lane & 7, l8 = (lane >> 3) & 1;
    int lq = lane >> 2, lr2 = (lane & 3) * 2;

    const float* Kp = K + (size_t)(bh * TT + t0) * NN;
    const float* Vp = V + (size_t)(bh * TT + t0) * NN;

    int ar = tid >> 4, ac8 = tid & 15;          // A: rows ar, ar+32 (of 64)
    uint32_t a_so = (uint32_t)(ar * 272 + ac8 * 16);

    uint4 ah4a, ah4b;
    auto loadA = [&](int m0g, int sl) {
        int r0 = sl * 64;
        int f = m0g * 128 + ac8 * 8;
        ah4a = rope_cvt8(Kp + (size_t)(r0 + ar) * NN + f,      t0 + r0 + ar,      f);
        ah4b = rope_cvt8(Kp + (size_t)(r0 + ar + 32) * NN + f, t0 + r0 + ar + 32, f);
    };
    auto storeA = [&](int buf) {
        char* ab = sm + KVA_0 + buf * KV_BUF_A;
        *(uint4*)(ab + a_so) = ah4a;
        *(uint4*)(ab + 8704 + a_so) = ah4b;
    };

    // stage A(0,0) + full V (128x256 fp16, resident)
    loadA(0, 0);
    storeA(0);
#pragma unroll
    for (int g = 0; g < 8; g++) {
        int idx = tid + g * 512;                // 0..4095
        int r = idx >> 5, c8 = idx & 31;
        uint4 vv = cvt8(Vp + (size_t)r * NN + c8 * 8);
        *(uint4*)(sm + KVV_SM + r * 528 + c8 * 16) = vv;
    }
    __syncthreads();

    float acc[2][8][4];
#pragma unroll
    for (int a = 0; a < 2; a++)
#pragma unroll
        for (int b = 0; b < 8; b++)
#pragma unroll
            for (int c = 0; c < 4; c++) acc[a][b][c] = 0.f;

    for (int it = 0; it < 4; it++) {
        int m0g = it >> 1, sl = it & 1;
        if (it < 3) loadA((it + 1) >> 1, (it + 1) & 1);
        uint32_t ab = sb + KVA_0 + (it & 1) * KV_BUF_A;
#pragma unroll
        for (int k0 = 0; k0 < 64; k0 += 16) {
            uint32_t ah[2][4];
#pragma unroll
            for (int mt = 0; mt < 2; mt++) {
                uint32_t off = (uint32_t)(((k0 + lmod8 + 8 * l16) * 136 +
                                           wm * 32 + mt * 16 + 8 * l8) * 2);
                ldsm4t(ah[mt], ab + off);
            }
#pragma unroll
            for (int np = 0; np < 4; np++) {
                uint32_t bh2[4];
                uint32_t off = (uint32_t)(((sl * 64 + k0 + lmod8 + 8 * l8) * 264 +
                                           wn * 64 + np * 16 + 8 * l16) * 2);
                ldsm4t(bh2, sb + KVV_SM + off);
#pragma unroll
                for (int mt = 0; mt < 2; mt++) {
                    mma_f16(acc[mt][2*np],   ah[mt], bh2);
                    mma_f16(acc[mt][2*np+1], ah[mt], bh2 + 2);
                }
            }
        }
        if (sl == 1) {                           // m-half complete: write fp16 S
            __half* Sp = g_S16 + (size_t)(bh * NCH + ch) * (NN * NN);
#pragma unroll
            for (int mt = 0; mt < 2; mt++)
#pragma unroll
                for (int nt = 0; nt < 8; nt++)
#pragma unroll
                    for (int h = 0; h < 2; h++) {
                        int rr = m0g * 128 + wm * 32 + mt * 16 + lq + 8 * h;
                        int cc = wn * 64 + nt * 8 + lr2;
                        *(uint32_t*)(Sp + (size_t)rr * NN + cc) =
                            cvtH2(acc[mt][nt][2*h], acc[mt][nt][2*h+1]);
                    }
#pragma unroll
            for (int a = 0; a < 2; a++)
#pragma unroll
                for (int b = 0; b < 8; b++)
#pragma unroll
                    for (int c = 0; c < 4; c++) acc[a][b][c] = 0.f;
        }
        if (it < 3) { storeA((it + 1) & 1); __syncthreads(); }
    }
}

// ---------------- kernel 3: exclusive prefix scan (fp16 in/out, fp32 accum) -----
__global__ void k_scan() {
    int g = blockIdx.x * blockDim.x + threadIdx.x;
    if (g >= BH * NN * NN / 4) return;
    int bh = g >> 14;
    int e4 = (g & 16383) << 2;
    size_t base = (size_t)bh * NCH * (NN * NN) + e4;
    uint2 vals[NCH - 1];
#pragma unroll
    for (int i = 0; i < NCH - 1; i++)
        vals[i] = *(const uint2*)(g_S16 + base + (size_t)i * (NN * NN));
    float r0 = 0.f, r1 = 0.f, r2 = 0.f, r3 = 0.f;
#pragma unroll
    for (int i = 0; i < NCH; i++) {
        size_t p = base + (size_t)i * (NN * NN);
        uint2 H;
        H.x = cvtH2(r0, r1);
        H.y = cvtH2(r2, r3);
        *(uint2*)(g_Sh + p) = H;
        if (i < NCH - 1) {
            float2 a = __half22float2(*(__half2*)&vals[i].x);
            float2 b = __half22float2(*(__half2*)&vals[i].y);
            r0 += a.x; r1 += a.y; r2 += b.x; r3 += b.y;
        }
    }
}

// ---------------- kernel 4: Out = QR@S_pref + strict_tril(QR@KR^T)@V ------------
#define AT_QBUF  18432
#define AT_B0    73728
#define AT_BUF_B 33792
#define AT_PH    141312
#define SMEM_ATTN 176128

#define S1_R_PACK 981476u
#define S1_C_PACK 54436u

__global__ void __launch_bounds__(512, 1) k_attn(const float* __restrict__ Q,
                                                 const float* __restrict__ K,
                                                 const float* __restrict__ V,
                                                 float* __restrict__ out) {
    extern __shared__ char sm[];
    uint32_t sb = smem_u32(sm);
    int tid = threadIdx.x, lane = tid & 31, wid = tid >> 5;
    int wm = wid >> 2, wn = wid & 3;
    int bh = blockIdx.x >> 4, ch = 15 - (blockIdx.x & 15);
    int t0 = ch * CC;
    int lm16 = lane & 15, l16 = lane >> 4, lmod8 = lane & 7, l8 = (lane >> 3) & 1;
    int lq = lane >> 2, lr2 = (lane & 3) * 2;

    const float* Qp = Q + (size_t)(bh * TT + t0) * NN;
    const float* Kp = K + (size_t)(bh * TT + t0) * NN;
    const float* Vp = V + (size_t)(bh * TT + t0) * NN;
    const __half* Sh = g_Sh + (size_t)(bh * NCH + ch) * (NN * NN);

    int sr = tid >> 2, sc8 = tid & 3;
    uint32_t s_so1 = (uint32_t)((sr * 72 + sc8 * 8) * 2);
    uint32_t s_so2 = (uint32_t)((sr * 72 + 32 + sc8 * 8) * 2);
    int vr = tid >> 5, vc8 = tid & 31;
    uint32_t v_so = (uint32_t)(vr * 528 + vc8 * 16);

    uint4 qa, qb, ka, kb;
    auto loadQK = [&](int sl) {
        int f1 = sl * 64 + sc8 * 8;
        float4 c1 = *(const float4*)(g_tabc + (t0 + sr) * 128 + (f1 >> 1));
        float4 s1 = *(const float4*)(g_tabs + (t0 + sr) * 128 + (f1 >> 1));
        float4 c2 = *(const float4*)(g_tabc + (t0 + sr) * 128 + (f1 >> 1) + 16);
        float4 s2 = *(const float4*)(g_tabs + (t0 + sr) * 128 + (f1 >> 1) + 16);
        qa = rope_cvt8_cs(Qp + (size_t)sr * NN + f1, c1, s1);
        qb = rope_cvt8_cs(Qp + (size_t)sr * NN + f1 + 32, c2, s2);
        ka = rope_cvt8_cs(Kp + (size_t)sr * NN + f1, c1, s1);
        kb = rope_cvt8_cs(Kp + (size_t)sr * NN + f1 + 32, c2, s2);
    };
    auto storeQK = [&](int sl) {
        char* qbuf = sm + sl * AT_QBUF;
        *(uint4*)(qbuf + s_so1) = qa;
        *(uint4*)(qbuf + s_so2) = qb;
        char* kbuf = sm + AT_B0 + (sl & 1) * AT_BUF_B;
        *(uint4*)(kbuf + s_so1) = ka;
        *(uint4*)(kbuf + s_so2) = kb;
    };
    auto cpS = [&](int buf, int sl) {
        uint32_t bb = sb + AT_B0 + buf * AT_BUF_B;
        int f0 = sl * 64;
#pragma unroll
        for (int v = tid; v < 2048; v += 512) {
            int r = v >> 5, c8 = v & 31;
            uint32_t so = (uint32_t)(r * 528 + c8 * 16);
            cpa16(bb + so, Sh + (size_t)(f0 + r) * NN + c8 * 8);
        }
    };
    uint4 vh0, vh1;
    auto loadV3 = [&](int sl) {
        vh0 = cvt8(Vp + (size_t)(sl * 32 + vr) * NN + vc8 * 8);
        vh1 = cvt8(Vp + (size_t)(sl * 32 + vr + 16) * NN + vc8 * 8);
    };
    auto storeV3 = [&](int buf) {
        char* bb = sm + AT_B0 + buf * AT_BUF_B;
        *(uint4*)(bb + v_so) = vh0;
        *(uint4*)(bb + 8448 + v_so) = vh1;
    };

    int pr = (S1_R_PACK >> (wid * 2)) & 3;
    int pc = (S1_C_PACK >> (wid * 2)) & 3;
    bool act1 = (wid < 10);

    // ======== Stage 1: P = QR @ KR^T, lower-triangle tiles only ================
    float acc1[2][4][4];
#pragma unroll
    for (int a = 0; a < 2; a++)
#pragma unroll
        for (int b = 0; b < 4; b++)
#pragma unroll
            for (int c = 0; c < 4; c++) acc1[a][b][c] = 0.f;

    loadQK(0);
    storeQK(0);
    __syncthreads();
    for (int sl = 0; sl < 4; sl++) {
        if (sl < 3) loadQK(sl + 1);
        else if (ch > 0) { cpS(0, 0); CP_COMMIT(); }
        if (act1) {
            uint32_t ab = sb + sl * AT_QBUF;
            uint32_t bb = sb + AT_B0 + (sl & 1) * AT_BUF_B;
#pragma unroll
            for (int k0 = 0; k0 < 64; k0 += 16) {
                uint32_t ah[2][4];
#pragma unroll
                for (int mt = 0; mt < 2; mt++) {
                    uint32_t off = (uint32_t)(((pr * 32 + mt * 16 + lm16) * 72 +
                                               k0 + 8 * l16) * 2);
                    ldsm4(ah[mt], ab + off);
                }
#pragma unroll
                for (int np = 0; np < 2; np++) {
                    uint32_t bh2[4];
                    uint32_t off = (uint32_t)(((pc * 32 + np * 16 + lmod8 + 8 * l16) * 72 +
                                               k0 + 8 * l8) * 2);
                    ldsm4(bh2, bb + off);
#pragma unroll
                    for (int mt = 0; mt < 2; mt++) {
                        mma_f16(acc1[mt][2*np],   ah[mt], bh2);
                        mma_f16(acc1[mt][2*np+1], ah[mt], bh2 + 2);
                    }
                }
            }
        }
        if (sl < 3) { storeQK(sl + 1); __syncthreads(); }
    }
    __syncthreads();
    if (ch > 0) { cpS(1, 1); CP_COMMIT(); }
    else loadV3(0);

    if (act1) {
#pragma unroll
        for (int mt = 0; mt < 2; mt++)
#pragma unroll
            for (int nt = 0; nt < 4; nt++)
#pragma unroll
                for (int h = 0; h < 2; h++) {
                    int rr = pr * 32 + mt * 16 + lq + 8 * h;
                    int cn = pc * 32 + nt * 8 + lr2;
                    float v0 = (cn     < rr) ? acc1[mt][nt][2*h]   : 0.f;
                    float v1 = (cn + 1 < rr) ? acc1[mt][nt][2*h+1] : 0.f;
                    uint32_t hbits = cvtH2(v0, v1);
                    uint32_t bo = (uint32_t)((rr * 136 + cn) * 2);
                    *(uint32_t*)(sm + AT_PH + bo) = hbits;
                }
    }
    if (ch > 0) CP_WAIT1();
    __syncthreads();

    // ======== Stage 2: D = QR @ S_pref (Q from persistent smem) ================
    float acc[2][8][4];
#pragma unroll
    for (int a = 0; a < 2; a++)
#pragma unroll
        for (int b = 0; b < 8; b++)
#pragma unroll
            for (int c = 0; c < 4; c++) acc[a][b][c] = 0.f;

    if (ch > 0) {
        for (int i = 0; i < 4; i++) {
            if (i >= 1 && i < 3) { cpS((i + 1) & 1, i + 1); CP_COMMIT(); }
            else if (i == 3) loadV3(0);
            uint32_t ab = sb + i * AT_QBUF;
            uint32_t bb = sb + AT_B0 + (i & 1) * AT_BUF_B;
#pragma unroll
            for (int k0 = 0; k0 < 64; k0 += 16) {
                uint32_t ah[2][4];
#pragma unroll
                for (int mt = 0; mt < 2; mt++) {
                    uint32_t off = (uint32_t)(((wm * 32 + mt * 16 + lm16) * 72 +
                                               k0 + 8 * l16) * 2);
                    ldsm4(ah[mt], ab + off);
                }
#pragma unroll
                for (int np = 0; np < 4; np++) {
                    uint32_t bh2[4];
                    uint32_t off = (uint32_t)(((k0 + lmod8 + 8 * l8) * 264 +
                                               wn * 64 + np * 16 + 8 * l16) * 2);
                    ldsm4t(bh2, bb + off);
#pragma unroll
                    for (int mt = 0; mt < 2; mt++) {
                        mma_f16(acc[mt][2*np],   ah[mt], bh2);
                        mma_f16(acc[mt][2*np+1], ah[mt], bh2 + 2);
                    }
                }
            }
            if (i < 3) { CP_WAIT0(); __syncthreads(); }
        }
        __syncthreads();
    }

    // ======== Stage 3: D += P @ V — skip slabs above warp's diagonal ===========
    storeV3(0);
    __syncthreads();
    for (int sl = 0; sl < 4; sl++) {
        if (sl < 3) loadV3(sl + 1);
        if (sl <= wm) {
            int s0 = sl * 32;
            uint32_t bb = sb + AT_B0 + (sl & 1) * AT_BUF_B;
#pragma unroll
            for (int k0 = 0; k0 < 32; k0 += 16) {
                uint32_t ah[2][4];
#pragma unroll
                for (int mt = 0; mt < 2; mt++) {
                    uint32_t off = (uint32_t)(((wm * 32 + mt * 16 + lm16) * 136 +
                                               s0 + k0 + 8 * l16) * 2);
                    ldsm4(ah[mt], sb + AT_PH + off);
                }
#pragma unroll
                for (int np = 0; np < 4; np++) {
                    uint32_t bh2[4];
                    uint32_t off = (uint32_t)(((k0 + lmod8 + 8 * l8) * 264 +
                                               wn * 64 + np * 16 + 8 * l16) * 2);
                    ldsm4t(bh2, bb + off);
#pragma unroll
                    for (int mt = 0; mt < 2; mt++) {
                        mma_f16(acc[mt][2*np],   ah[mt], bh2);
                        mma_f16(acc[mt][2*np+1], ah[mt], bh2 + 2);
                    }
                }
            }
        }
        if (sl < 3) { storeV3((sl + 1) & 1); __syncthreads(); }
    }

    // epilogue
#pragma unroll
    for (int mt = 0; mt < 2; mt++)
#pragma unroll
        for (int nt = 0; nt < 8; nt++)
#pragma unroll
            for (int h = 0; h < 2; h++) {
                int rr = wm * 32 + mt * 16 + lq + 8 * h;
                int cc = wn * 64 + nt * 8 + lr2;
                float2 o; o.x = acc[mt][nt][2*h]; o.y = acc[mt][nt][2*h+1];
                *(float2*)(out + (size_t)(bh * TT + t0 + rr) * NN + cc) = o;
            }
}

// ---------------- launcher -------------------------------------------------------
extern "C" void kernel_launch(void* const* d_in, const int* in_sizes, int n_in,
                              void* d_out, int out_size) {
    const float* Q = (const float*)d_in[0];
    const float* K = (const float*)d_in[1];
    const float* V = (const float*)d_in[2];
    float* out = (float*)d_out;

    static bool attr_set = false;
    if (!attr_set) {
        cudaFuncSetAttribute(k_kv,   cudaFuncAttributeMaxDynamicSharedMemorySize, SMEM_KV);
        cudaFuncSetAttribute(k_attn, cudaFuncAttributeMaxDynamicSharedMemorySize, SMEM_ATTN);
        attr_set = true;
    }

    k_tables<<<512, 512>>>();
    k_kv<<<BH * (NCH - 1), 512, SMEM_KV>>>(K, V);
    k_scan<<<(BH * NN * NN / 4 + 255) / 256, 256>>>();
    k_attn<<<BH * NCH, 512, SMEM_ATTN>>>(Q, K, V, out);
}